// round 12
// baseline (speedup 1.0000x reference)
#include <cuda_runtime.h>
#include <cuda_bf16.h>
#include <cstdint>

// Problem constants (fixed by the reference)
#define NN   100000
#define EE   3200000

// ---------------- scratch (device globals: no allocation allowed) ----------
#define NS       ((size_t)51200000)       // NN*512 floats
#define A_OFF    ((size_t)0)              // fp32 ping
#define B_OFF    (NS)                     // fp32 GEMM ACC / pre-norm H
#define C_OFF    (2*NS)                   // fp32 pong
#define U_OFF    (3*NS)                   // NN*64
#define T1_OFF   (U_OFF + 6400000)        // NN*16
#define T2_OFF   (T1_OFF + 1600000)       // NN*16
#define BUF_TOTAL (T2_OFF + 1600000)

__device__ float g_buf[BUF_TOTAL];
__device__ float g_deg[NN];
__device__ float g_dinv[NN];
__device__ int   g_off[NN + 1];
__device__ int   g_cursor[NN];
__device__ int   g_src[EE];
__device__ float g_w[EE];
__device__ float g_stats[1024];
__device__ int   g_is64;
__device__ int   g_total;

// bf16 activation ping/pong + weights
__device__ __nv_bfloat16 g_ah[(size_t)NN * 512];
__device__ __nv_bfloat16 g_al[(size_t)NN * 512];
__device__ __nv_bfloat16 g_bh[(size_t)NN * 512];
__device__ __nv_bfloat16 g_bl[(size_t)NN * 512];
__device__ __nv_bfloat16 g_wb[5 * 2 * 262144];
__device__ __nv_bfloat16 g_w3b[2 * 64 * 512];   // W3 transposed [64(N)][512(K)] hi/lo

#define NGEMM_CTAS 3128     // 782 row blocks x 4 col blocks
#define NPROP_CTAS 50000    // 4 quarters x 12500 (8 nodes each)

// ---------------- PTX helpers (baseline ISA only — no 'a' features) --------
__device__ __forceinline__ uint32_t smem_u32(const void* p) {
    uint32_t a;
    asm("{ .reg .u64 t; cvta.to.shared.u64 t, %1; cvt.u32.u64 %0, t; }"
        : "=r"(a) : "l"(p));
    return a;
}

#define SWZ64(off) ((off) ^ (((off) >> 3) & 0x30))

#define LDSM4(r, addr) \
    asm volatile("ldmatrix.sync.aligned.m8n8.x4.shared.b16 {%0,%1,%2,%3}, [%4];" \
        : "=r"((r)[0]), "=r"((r)[1]), "=r"((r)[2]), "=r"((r)[3]) : "r"(addr))
#define LDSM2(r, addr) \
    asm volatile("ldmatrix.sync.aligned.m8n8.x2.shared.b16 {%0,%1}, [%2];" \
        : "=r"((r)[0]), "=r"((r)[1]) : "r"(addr))
#define MMA_BF16(d, a, b) \
    asm volatile("mma.sync.aligned.m16n8k16.row.col.f32.bf16.bf16.f32 " \
        "{%0,%1,%2,%3}, {%4,%5,%6,%7}, {%8,%9}, {%0,%1,%2,%3};" \
        : "+f"((d)[0]), "+f"((d)[1]), "+f"((d)[2]), "+f"((d)[3]) \
        : "r"((a)[0]), "r"((a)[1]), "r"((a)[2]), "r"((a)[3]), \
          "r"((b)[0]), "r"((b)[1]))
#define CP_ASYNC16(smaddr, gptr, sz) \
    asm volatile("cp.async.cg.shared.global [%0], [%1], 16, %2;" \
        :: "r"(smaddr), "l"(gptr), "r"(sz) : "memory")

// ---------------- bf16 split helpers ----------------
__device__ __forceinline__ void split1(float v, __nv_bfloat16& h, __nv_bfloat16& l) {
    h = __float2bfloat16(v);
    l = __float2bfloat16(v - __bfloat162float(h));
}
__device__ __forceinline__ void split4_store(float4 v, __nv_bfloat16* ph, __nv_bfloat16* pl) {
    union { __nv_bfloat16 b[4]; uint2 u; } H, L;
    split1(v.x, H.b[0], L.b[0]);
    split1(v.y, H.b[1], L.b[1]);
    split1(v.z, H.b[2], L.b[2]);
    split1(v.w, H.b[3], L.b[3]);
    *(uint2*)ph = H.u;
    *(uint2*)pl = L.u;
}

// ---------------- edge dtype detection ----------------
__global__ void k_detect(const int* __restrict__ ei32) {
    __shared__ int any;
    if (threadIdx.x == 0) any = 0;
    __syncthreads();
    for (int i = threadIdx.x; i < 8192; i += blockDim.x)
        if (ei32[2 * i + 1] != 0) any = 1;
    __syncthreads();
    if (threadIdx.x == 0) g_is64 = (any == 0) ? 1 : 0;
}
__device__ __forceinline__ int edge_val(const void* ei, size_t idx) {
    if (g_is64) return (int)((const long long*)ei)[idx];
    return ((const int*)ei)[idx];
}

// ---------------- graph preprocessing ----------------
__global__ void k_zero_init() {
    int i = blockIdx.x * blockDim.x + threadIdx.x;
    if (i < NN) { g_deg[i] = 0.f; g_cursor[i] = 0; }
    if (i < 1024) g_stats[i] = 0.f;
    if (i == 0) g_total = 0;
}
__global__ void k_zero_stats() {
    int i = blockIdx.x * blockDim.x + threadIdx.x;
    if (i < 1024) g_stats[i] = 0.f;
}
__global__ void k_deg(const void* __restrict__ ei) {
    int e = blockIdx.x * blockDim.x + threadIdx.x;
    if (e >= EE) return;
    atomicAdd(&g_deg[edge_val(ei, (size_t)EE + e)], 1.f);
}
// CSR range allocation (warp scan + 1 atomic/warp) + dinv, fused.
__global__ void k_alloc() {
    int i = blockIdx.x * blockDim.x + threadIdx.x;
    int lane = threadIdx.x & 31;
    float df = (i < NN) ? g_deg[i] : 0.f;
    if (i < NN) g_dinv[i] = df > 0.f ? rsqrtf(df) : 0.f;
    int d = (int)df;
    int sum = d;
#pragma unroll
    for (int o = 1; o < 32; o <<= 1) {
        int t = __shfl_up_sync(0xFFFFFFFFu, sum, o);
        if (lane >= o) sum += t;
    }
    int excl = sum - d;
    int wtot = __shfl_sync(0xFFFFFFFFu, sum, 31);
    int base = 0;
    if (lane == 0) base = atomicAdd(&g_total, wtot);
    base = __shfl_sync(0xFFFFFFFFu, base, 0);
    if (i < NN) g_off[i] = base + excl;
}
__global__ void k_scatter(const void* __restrict__ ei) {
    int e = blockIdx.x * blockDim.x + threadIdx.x;
    if (e >= EE) return;
    int r = edge_val(ei, (size_t)e);
    int c = edge_val(ei, (size_t)EE + e);
    int pos = g_off[c] + atomicAdd(&g_cursor[c], 1);
    g_src[pos] = r;
    g_w[pos] = g_dinv[r] * g_dinv[c];
}

// x (fp32 [NN,128]) -> bf16 hi/lo into cols 0..127 of g_ah/g_al
__global__ void k_xsplit(const float* __restrict__ x) {
    int idx = blockIdx.x * blockDim.x + threadIdx.x;
    if (idx >= NN * 32) return;
    int m = idx >> 5, c = (idx & 31) * 4;
    float4 v = ((const float4*)x)[idx];
    split4_store(v, &g_ah[(size_t)m * 512 + c], &g_al[(size_t)m * 512 + c]);
}

// weight transpose+split: W [512(K)][512(N)] fp32 -> g_wb[wsel] as [N][K] bf16 hi/lo
__global__ void k_wsplit(const float* __restrict__ W, int wsel) {
    int idx = blockIdx.x * blockDim.x + threadIdx.x;
    if (idx >= 262144) return;
    int n = idx >> 9, k = idx & 511;
    float v = W[(size_t)k * 512 + n];
    __nv_bfloat16 h, l;
    split1(v, h, l);
    g_wb[(size_t)wsel * 524288 + (size_t)n * 512 + k] = h;
    g_wb[(size_t)wsel * 524288 + 262144 + (size_t)n * 512 + k] = l;
}

// W3 (4,512,16) -> g_w3b [n=k*16+j][i] bf16 hi/lo
__global__ void k_w3split(const float* __restrict__ W3) {
    int idx = blockIdx.x * blockDim.x + threadIdx.x;
    if (idx >= 32768) return;
    int k = idx >> 13;
    int r = idx & 8191;
    int i = r >> 4, j = r & 15;
    int n = k * 16 + j;
    __nv_bfloat16 h, l;
    split1(W3[idx], h, l);
    g_w3b[n * 512 + i] = h;
    g_w3b[32768 + n * 512 + i] = l;
}

// ---------------- generic CSR gather prop (layer 1 / layer 3) --------------
template <int G>
__global__ void k_prop(const float* __restrict__ in_ext, size_t in_off, int in_s4,
                       size_t out_off, int out_s4, float* out_ext,
                       size_t add_off, int add_s4, int has_add,
                       const float* __restrict__ bias, int bcol, int cbase4) {
    const int per = 256 / G;
    int node = blockIdx.x * per + (int)(threadIdx.x / G);
    int lane = threadIdx.x % G;
    if (node >= NN) return;
    int s = g_off[node];
    int e = s + (int)__ldg(&g_deg[node]);
    const float4* in4 = in_ext ? (const float4*)in_ext : (const float4*)(g_buf + in_off);
    float4 acc = make_float4(0.f, 0.f, 0.f, 0.f);
    int p = s;
    for (; p + 1 < e; p += 2) {
        int   j0 = __ldg(&g_src[p]),     j1 = __ldg(&g_src[p + 1]);
        float w0 = __ldg(&g_w[p]),       w1 = __ldg(&g_w[p + 1]);
        float4 v0 = __ldg(&in4[(size_t)j0 * in_s4 + cbase4 + lane]);
        float4 v1 = __ldg(&in4[(size_t)j1 * in_s4 + cbase4 + lane]);
        acc.x += w0 * v0.x + w1 * v1.x;
        acc.y += w0 * v0.y + w1 * v1.y;
        acc.z += w0 * v0.z + w1 * v1.z;
        acc.w += w0 * v0.w + w1 * v1.w;
    }
    if (p < e) {
        int   j  = __ldg(&g_src[p]);
        float wt = __ldg(&g_w[p]);
        float4 v = __ldg(&in4[(size_t)j * in_s4 + cbase4 + lane]);
        acc.x += wt * v.x; acc.y += wt * v.y;
        acc.z += wt * v.z; acc.w += wt * v.w;
    }
    if (has_add) {
        float4 a = ((const float4*)(g_buf + add_off))[(size_t)node * add_s4 + cbase4 + lane];
        acc.x += a.x; acc.y += a.y; acc.z += a.z; acc.w += a.w;
    }
    if (bias) {
        float4 b = ((const float4*)bias)[cbase4 + lane];
        acc.x += b.x; acc.y += b.y; acc.z += b.z; acc.w += b.w;
    }
    float4* out4 = out_ext ? (float4*)out_ext : (float4*)(g_buf + out_off);
    out4[(size_t)node * out_s4 + cbase4 + lane] = acc;
    if (bcol >= 0) {
        size_t bo = (size_t)node * 512 + bcol + lane * 4;
        split4_store(acc, &g_ah[bo], &g_al[bo]);
    }
}

// ---------------- device bodies: GEMM tile & quarter-prop ------------------
// GEMM: bf16x3 mma.sync, CTA tile 128x128, K=512 in 16 chunks of 32,
// cp.async 2-stage pipeline; A selected by asel (0: g_ah/g_al, 1: g_bh/g_bl).
#define GSM_TOTAL 65536

__device__ __forceinline__ void gemm_dev(int bid, char* smem, int wsel, int asel,
                                         size_t c_off, int M,
                                         const float* __restrict__ bias,
                                         int relu, int accum) {
    uint32_t sb = smem_u32(smem);
    int tid = threadIdx.x, wid = tid >> 5, lane = tid & 31;
    int rowBase = (bid >> 2) * 128, colBase = (bid & 3) * 128;
    int warpM = (wid & 1) * 64, warpN = (wid >> 1) * 32;
    const __nv_bfloat16* Ahi = asel ? g_bh : g_ah;
    const __nv_bfloat16* Alo = asel ? g_bl : g_al;
    const __nv_bfloat16* Bhi = g_wb + (size_t)wsel * 524288;
    const __nv_bfloat16* Blo = Bhi + 262144;

    float acc[4][4][4];
#pragma unroll
    for (int mi = 0; mi < 4; ++mi)
#pragma unroll
        for (int ni = 0; ni < 4; ++ni)
#pragma unroll
            for (int q = 0; q < 4; ++q) acc[mi][ni][q] = 0.f;

    auto load_stage = [&](int c, int st) {
#pragma unroll
        for (int i = 0; i < 8; ++i) {
            int it = tid + i * 256;
            int mat = it >> 9;
            int idx = it & 511;
            int r = idx >> 2, u = idx & 3;
            uint32_t so = sb + (uint32_t)st * 32768 + (uint32_t)mat * 8192 +
                          SWZ64((uint32_t)(r * 64 + u * 16));
            const __nv_bfloat16* src;
            int gr, sz = 16;
            if (mat == 0)      { src = Ahi; gr = rowBase + r; if (gr >= M) { gr = 0; sz = 0; } }
            else if (mat == 1) { src = Alo; gr = rowBase + r; if (gr >= M) { gr = 0; sz = 0; } }
            else if (mat == 2) { src = Bhi; gr = colBase + r; }
            else               { src = Blo; gr = colBase + r; }
            const void* gp = src + (size_t)gr * 512 + c * 32 + u * 8;
            CP_ASYNC16(so, gp, sz);
        }
        asm volatile("cp.async.commit_group;" ::: "memory");
    };

    load_stage(0, 0);
    for (int c = 0; c < 16; ++c) {
        if (c + 1 < 16) {
            load_stage(c + 1, (c + 1) & 1);
            asm volatile("cp.async.wait_group 1;" ::: "memory");
        } else {
            asm volatile("cp.async.wait_group 0;" ::: "memory");
        }
        __syncthreads();
        uint32_t sbase = sb + (uint32_t)(c & 1) * 32768;
#pragma unroll
        for (int ks = 0; ks < 2; ++ks) {
            uint32_t bH[4][2], bL[4][2];
            int bl = lane & 15;
            int brow0 = warpN + (bl & 7);
            uint32_t bunit = ks * 2 + ((bl >> 3) & 1);
#pragma unroll
            for (int ni = 0; ni < 4; ++ni) {
                uint32_t off = SWZ64((uint32_t)((brow0 + ni * 8) * 64 + bunit * 16));
                LDSM2(bH[ni], sbase + 16384 + off);
                LDSM2(bL[ni], sbase + 24576 + off);
            }
            int arow = warpM + (lane & 15);
            uint32_t aunit = ks * 2 + (lane >> 4);
#pragma unroll
            for (int mi = 0; mi < 4; ++mi) {
                uint32_t aH[4], aL[4];
                uint32_t off = SWZ64((uint32_t)((arow + mi * 16) * 64 + aunit * 16));
                LDSM4(aH, sbase + off);
                LDSM4(aL, sbase + 8192 + off);
#pragma unroll
                for (int ni = 0; ni < 4; ++ni) {
                    MMA_BF16(acc[mi][ni], aH, bH[ni]);
                    MMA_BF16(acc[mi][ni], aH, bL[ni]);
                    MMA_BF16(acc[mi][ni], aL, bH[ni]);
                }
            }
        }
        __syncthreads();
    }

    float* C = g_buf + c_off;
#pragma unroll
    for (int mi = 0; mi < 4; ++mi) {
        int r0 = rowBase + warpM + mi * 16 + (lane >> 2);
#pragma unroll
        for (int ni = 0; ni < 4; ++ni) {
            int cc = colBase + warpN + ni * 8 + (lane & 3) * 2;
            float2 v0 = make_float2(acc[mi][ni][0], acc[mi][ni][1]);
            float2 v1 = make_float2(acc[mi][ni][2], acc[mi][ni][3]);
            if (bias) {
                float2 bb = *(const float2*)&bias[cc];
                v0.x += bb.x; v0.y += bb.y;
                v1.x += bb.x; v1.y += bb.y;
            }
            if (r0 < M) {
                float* p = C + (size_t)r0 * 512 + cc;
                if (accum) { float2 o = *(float2*)p; v0.x += o.x; v0.y += o.y; }
                if (relu) { v0.x = fmaxf(v0.x, 0.f); v0.y = fmaxf(v0.y, 0.f); }
                *(float2*)p = v0;
            }
            if (r0 + 8 < M) {
                float* p = C + (size_t)(r0 + 8) * 512 + cc;
                if (accum) { float2 o = *(float2*)p; v1.x += o.x; v1.y += o.y; }
                if (relu) { v1.x = fmaxf(v1.x, 0.f); v1.y = fmaxf(v1.y, 0.f); }
                *(float2*)p = v1;
            }
        }
    }
}

// Quarter-prop: G=32, 8 nodes/CTA, quarter q = pb/12500 (CTAs ordered so
// quarters run roughly sequentially -> 51MB gather input stays L2-resident).
__device__ __forceinline__ void prop_dev(int pb, size_t in_off, size_t out_off,
                                         int emit_sel) {
    int q = pb / 12500, ng = pb - q * 12500;
    int tid = threadIdx.x;
    int node = ng * 8 + (tid >> 5);
    int lane = tid & 31;
    int cbase4 = q * 32;
    if (node >= NN) return;
    int s = g_off[node];
    int e = s + (int)__ldg(&g_deg[node]);
    const float4* in4 = (const float4*)(g_buf + in_off);
    float4 acc = make_float4(0.f, 0.f, 0.f, 0.f);
    int p = s;
    for (; p + 1 < e; p += 2) {
        int   j0 = __ldg(&g_src[p]),     j1 = __ldg(&g_src[p + 1]);
        float w0 = __ldg(&g_w[p]),       w1 = __ldg(&g_w[p + 1]);
        float4 v0 = __ldg(&in4[(size_t)j0 * 128 + cbase4 + lane]);
        float4 v1 = __ldg(&in4[(size_t)j1 * 128 + cbase4 + lane]);
        acc.x += w0 * v0.x + w1 * v1.x;
        acc.y += w0 * v0.y + w1 * v1.y;
        acc.z += w0 * v0.z + w1 * v1.z;
        acc.w += w0 * v0.w + w1 * v1.w;
    }
    if (p < e) {
        int   j  = __ldg(&g_src[p]);
        float wt = __ldg(&g_w[p]);
        float4 v = __ldg(&in4[(size_t)j * 128 + cbase4 + lane]);
        acc.x += wt * v.x; acc.y += wt * v.y;
        acc.z += wt * v.z; acc.w += wt * v.w;
    }
    ((float4*)(g_buf + out_off))[(size_t)node * 128 + cbase4 + lane] = acc;
    __nv_bfloat16* oh = emit_sel ? g_bh : g_ah;
    __nv_bfloat16* ol = emit_sel ? g_bl : g_al;
    size_t bo = (size_t)node * 512 + q * 128 + lane * 4;
    split4_store(acc, &oh[bo], &ol[bo]);
}

// Fused launch: CTAs [0, NGEMM) = GEMM(wsel, A=asel); rest = prop(in->out).
__global__ __launch_bounds__(256, 2)
void k_fused(int wsel, int asel, size_t c_off,
             const float* __restrict__ bias, int relu, int accum,
             size_t pin, size_t pout, int emit_sel) {
    extern __shared__ char smem[];
    if (blockIdx.x < NGEMM_CTAS)
        gemm_dev(blockIdx.x, smem, wsel, asel, c_off, NN, bias, relu, accum);
    else
        prop_dev(blockIdx.x - NGEMM_CTAS, pin, pout, emit_sel);
}

// Standalone GEMM (layer-1 GEMM and final layer-2 GEMM)
__global__ __launch_bounds__(256, 2)
void k_gemm_mma(int wsel, int asel, size_t c_off, int M,
                const float* __restrict__ bias, int relu, int accum) {
    extern __shared__ char smem[];
    gemm_dev(blockIdx.y * 4 + blockIdx.x, smem, wsel, asel, c_off, M, bias, relu, accum);
}

// ---------------- bf16x3 mma.sync GEMM, 128x64 tile (layer 3) --------------
#define GSM64_TOTAL 49152

__global__ __launch_bounds__(256, 2)
void k_gemm_mma64(int M) {
    extern __shared__ char smem[];
    uint32_t sb = smem_u32(smem);
    int tid = threadIdx.x, wid = tid >> 5, lane = tid & 31;
    int rowBase = blockIdx.x * 128;
    int warpM = (wid & 3) * 32, warpN = (wid >> 2) * 32;

    float acc[2][4][4];
#pragma unroll
    for (int mi = 0; mi < 2; ++mi)
#pragma unroll
        for (int ni = 0; ni < 4; ++ni)
#pragma unroll
            for (int q = 0; q < 4; ++q) acc[mi][ni][q] = 0.f;

    auto load_stage = [&](int c, int st) {
#pragma unroll
        for (int i = 0; i < 6; ++i) {
            int it = tid + i * 256;
            uint32_t so;
            const void* gp;
            int sz = 16;
            if (it < 1024) {
                int hl = it >> 9, idx = it & 511;
                int r = idx >> 2, u = idx & 3;
                so = sb + (uint32_t)st * 24576 + (uint32_t)hl * 8192 +
                     SWZ64((uint32_t)(r * 64 + u * 16));
                int gr = rowBase + r;
                if (gr >= M) { gr = 0; sz = 0; }
                const __nv_bfloat16* src = hl ? g_al : g_ah;
                gp = src + (size_t)gr * 512 + c * 32 + u * 8;
            } else {
                int itb = it - 1024;
                int hl = itb >> 8, idx = itb & 255;
                int r = idx >> 2, u = idx & 3;
                so = sb + (uint32_t)st * 24576 + 16384 + (uint32_t)hl * 4096 +
                     SWZ64((uint32_t)(r * 64 + u * 16));
                gp = g_w3b + (size_t)hl * 32768 + (size_t)r * 512 + c * 32 + u * 8;
            }
            CP_ASYNC16(so, gp, sz);
        }
        asm volatile("cp.async.commit_group;" ::: "memory");
    };

    load_stage(0, 0);
    for (int c = 0; c < 16; ++c) {
        if (c + 1 < 16) {
            load_stage(c + 1, (c + 1) & 1);
            asm volatile("cp.async.wait_group 1;" ::: "memory");
        } else {
            asm volatile("cp.async.wait_group 0;" ::: "memory");
        }
        __syncthreads();
        uint32_t sbase = sb + (uint32_t)(c & 1) * 24576;
#pragma unroll
        for (int ks = 0; ks < 2; ++ks) {
            uint32_t bH[4][2], bL[4][2];
            int bl = lane & 15;
            int brow0 = warpN + (bl & 7);
            uint32_t bunit = ks * 2 + ((bl >> 3) & 1);
#pragma unroll
            for (int ni = 0; ni < 4; ++ni) {
                uint32_t off = SWZ64((uint32_t)((brow0 + ni * 8) * 64 + bunit * 16));
                LDSM2(bH[ni], sbase + 16384 + off);
                LDSM2(bL[ni], sbase + 20480 + off);
            }
            int arow = warpM + (lane & 15);
            uint32_t aunit = ks * 2 + (lane >> 4);
#pragma unroll
            for (int mi = 0; mi < 2; ++mi) {
                uint32_t aH[4], aL[4];
                uint32_t off = SWZ64((uint32_t)((arow + mi * 16) * 64 + aunit * 16));
                LDSM4(aH, sbase + off);
                LDSM4(aL, sbase + 8192 + off);
#pragma unroll
                for (int ni = 0; ni < 4; ++ni) {
                    MMA_BF16(acc[mi][ni], aH, bH[ni]);
                    MMA_BF16(acc[mi][ni], aH, bL[ni]);
                    MMA_BF16(acc[mi][ni], aL, bH[ni]);
                }
            }
        }
        __syncthreads();
    }

    float* C = g_buf + U_OFF;
#pragma unroll
    for (int mi = 0; mi < 2; ++mi) {
        int r0 = rowBase + warpM + mi * 16 + (lane >> 2);
#pragma unroll
        for (int ni = 0; ni < 4; ++ni) {
            int cc = warpN + ni * 8 + (lane & 3) * 2;
            if (r0 < M)
                *(float2*)(C + (size_t)r0 * 64 + cc) =
                    make_float2(acc[mi][ni][0], acc[mi][ni][1]);
            if (r0 + 8 < M)
                *(float2*)(C + (size_t)(r0 + 8) * 64 + cc) =
                    make_float2(acc[mi][ni][2], acc[mi][ni][3]);
        }
    }
}

// ---------------- GraphNorm ----------------
__global__ void k_stats(size_t x_off) {
    const float* x = g_buf + x_off;
    int col = threadIdx.x;
    float s = 0.f, q = 0.f;
    for (int i = blockIdx.x; i < NN; i += gridDim.x) {
        float v = x[(size_t)i * 512 + col];
        s += v;
        q += v * v;
    }
    atomicAdd(&g_stats[col], s);
    atomicAdd(&g_stats[512 + col], q);
}
__global__ void k_gnorm(size_t x_off, size_t out_off,
                        const float* __restrict__ w,
                        const float* __restrict__ b,
                        const float* __restrict__ a, int emit_bf16) {
    const float* x = g_buf + x_off;
    float* out = g_buf + out_off;
    int col = threadIdx.x;
    const float invn = 1.f / (float)NN;
    float m  = g_stats[col] * invn;
    float am = a[col] * m;
    float var = g_stats[512 + col] * invn - 2.f * am * m + am * am;
    float sc = rsqrtf(var + 1e-5f) * w[col];
    float sh = b[col];
    for (int i = blockIdx.x; i < NN; i += gridDim.x) {
        float v = (x[(size_t)i * 512 + col] - am) * sc + sh;
        out[(size_t)i * 512 + col] = v;
        if (emit_bf16) {
            __nv_bfloat16 h, l;
            split1(v, h, l);
            g_ah[(size_t)i * 512 + col] = h;
            g_al[(size_t)i * 512 + col] = l;
        }
    }
}

// ---------------- launcher ----------------
extern "C" void kernel_launch(void* const* d_in, const int* in_sizes, int n_in,
                              void* d_out, int out_size) {
    const float* x    = (const float*)d_in[0];
    const void*  ei   = d_in[1];
    const float* W1   = (const float*)d_in[2];
    const float* b1   = (const float*)d_in[3];
    const float* W2   = (const float*)d_in[4];
    const float* b2   = (const float*)d_in[5];
    const float* W3   = (const float*)d_in[6];
    const float* b3   = (const float*)d_in[7];
    const float* gn1w = (const float*)d_in[8];
    const float* gn1b = (const float*)d_in[9];
    const float* gn1a = (const float*)d_in[10];
    const float* gn2w = (const float*)d_in[11];
    const float* gn2b = (const float*)d_in[12];
    const float* gn2a = (const float*)d_in[13];
    float* out = (float*)d_out;

    cudaFuncSetAttribute(k_gemm_mma, cudaFuncAttributeMaxDynamicSharedMemorySize, GSM_TOTAL);
    cudaFuncSetAttribute(k_fused, cudaFuncAttributeMaxDynamicSharedMemorySize, GSM_TOTAL);
    cudaFuncSetAttribute(k_gemm_mma64, cudaFuncAttributeMaxDynamicSharedMemorySize, GSM64_TOTAL);

    // graph preprocessing
    k_detect<<<1, 256>>>((const int*)ei);
    k_zero_init<<<(NN + 255) / 256, 256>>>();
    k_deg<<<(EE + 255) / 256, 256>>>(ei);
    k_alloc<<<(NN + 255) / 256, 256>>>();
    k_scatter<<<(EE + 255) / 256, 256>>>(ei);

    // weight splits (independent of graph)
    k_wsplit<<<1024, 256>>>(W1, 0);
    k_wsplit<<<1024, 256>>>(W2, 1);
    k_wsplit<<<1024, 256>>>(W2 + 262144, 2);
    k_wsplit<<<1024, 256>>>(W2 + 524288, 3);
    k_wsplit<<<1024, 256>>>(W2 + 786432, 4);
    k_w3split<<<128, 256>>>(W3);

    const size_t P0 = A_OFF;                       // [NN,128] fp32 ping
    const size_t P1 = A_OFF + (size_t)NN * 128;    // [NN,128] fp32 pong
    dim3 gg(4, (NN + 127) / 128);
    const int FUSED_CTAS = NGEMM_CTAS + NPROP_CTAS;

    // ---- layer 1: width-128 props; bf16 concat cols fill g_ah/g_al ----
    k_xsplit<<<(NN * 32 + 255) / 256, 256>>>(x);
    k_prop<32><<<(NN + 7) / 8, 256>>>(x, 0, 32, P0, 32, nullptr, 0, 0, 0, nullptr, 128, 0);
    k_prop<32><<<(NN + 7) / 8, 256>>>(nullptr, P0, 32, P1, 32, nullptr, 0, 0, 0, nullptr, 256, 0);
    k_prop<32><<<(NN + 7) / 8, 256>>>(nullptr, P1, 32, P0, 32, nullptr, 0, 0, 0, nullptr, 384, 0);
    k_gemm_mma<<<gg, 256, GSM_TOTAL>>>(0, 0, B_OFF, NN, b1, 1, 0);

    // graphnorm 1: B -> C fp32 h0 (+bf16 into P0 pair g_ah/g_al)
    k_stats<<<512, 512>>>(B_OFF);
    k_gnorm<<<512, 512>>>(B_OFF, C_OFF, gn1w, gn1b, gn1a, 1);

    // ---- layer 2: fused [gemm(k, h_k) || prop(h_k -> h_{k+1})] ----
    // F1: gemm wsel=1 reads bf16 ping (g_ah); prop h0(C)->h1(A), emit pong
    k_fused<<<FUSED_CTAS, 256, GSM_TOTAL>>>(1, 0, B_OFF, b2, 0, 0, C_OFF, A_OFF, 1);
    // F2: gemm wsel=2 reads pong; prop h1(A)->h2(C), emit ping
    k_fused<<<FUSED_CTAS, 256, GSM_TOTAL>>>(2, 1, B_OFF, nullptr, 0, 1, A_OFF, C_OFF, 0);
    // F3: gemm wsel=3 reads ping; prop h2(C)->h3(A), emit pong
    k_fused<<<FUSED_CTAS, 256, GSM_TOTAL>>>(3, 0, B_OFF, nullptr, 0, 1, C_OFF, A_OFF, 1);
    // final: gemm wsel=4 reads pong, accum + relu
    k_gemm_mma<<<gg, 256, GSM_TOTAL>>>(4, 1, B_OFF, NN, nullptr, 1, 1);

    // graphnorm 2: B -> C (H2 fp32 + bf16 into ping for layer-3 mma)
    k_zero_stats<<<4, 256>>>();
    k_stats<<<512, 512>>>(B_OFF);
    k_gnorm<<<512, 512>>>(B_OFF, C_OFF, gn2w, gn2b, gn2a, 1);

    // ---- layer 3: U = H2 @ W3t (mma), then Horner on 16-wide features ----
    k_gemm_mma64<<<(NN + 127) / 128, 256, GSM64_TOTAL>>>(NN);
    k_prop<4><<<(NN + 63) / 64, 256>>>(nullptr, U_OFF + 48, 16, T1_OFF, 4, nullptr, U_OFF + 32, 16, 1, nullptr, -1, 0);
    k_prop<4><<<(NN + 63) / 64, 256>>>(nullptr, T1_OFF, 4, T2_OFF, 4, nullptr, U_OFF + 16, 16, 1, nullptr, -1, 0);
    k_prop<4><<<(NN + 63) / 64, 256>>>(nullptr, T2_OFF, 4, 0, 4, out, U_OFF, 16, 1, b3, -1, 0);
}

// round 13
// speedup vs baseline: 1.2932x; 1.2932x over previous
#include <cuda_runtime.h>
#include <cuda_bf16.h>
#include <cstdint>

// Problem constants (fixed by the reference)
#define NN   100000
#define EE   3200000

// ---------------- scratch (device globals: no allocation allowed) ----------
#define NS       ((size_t)51200000)       // NN*512 floats
#define A_OFF    ((size_t)0)              // fp32 ping
#define B_OFF    (NS)                     // fp32 GEMM ACC / pre-norm H
#define C_OFF    (2*NS)                   // fp32 pong
#define U_OFF    (3*NS)                   // NN*64
#define T1_OFF   (U_OFF + 6400000)        // NN*16
#define T2_OFF   (T1_OFF + 1600000)       // NN*16
#define BUF_TOTAL (T2_OFF + 1600000)

__device__ float g_buf[BUF_TOTAL];
__device__ float g_deg[NN];
__device__ float g_dinv[NN];
__device__ int   g_off[NN + 1];
__device__ int   g_cursor[NN];
__device__ int   g_src[EE];
__device__ float g_w[EE];
__device__ float g_stats[1024];
__device__ int   g_is64;
__device__ int   g_total;

// bf16 split buffers: activations hi/lo [NN,512], weights hi/lo
__device__ __nv_bfloat16 g_ah[(size_t)NN * 512];
__device__ __nv_bfloat16 g_al[(size_t)NN * 512];
__device__ __nv_bfloat16 g_wb[5 * 2 * 262144];
__device__ __nv_bfloat16 g_w3b[2 * 64 * 512];   // W3 transposed [64(N)][512(K)] hi/lo

// ---------------- PTX helpers (baseline ISA only — no 'a' features) --------
__device__ __forceinline__ uint32_t smem_u32(const void* p) {
    uint32_t a;
    asm("{ .reg .u64 t; cvta.to.shared.u64 t, %1; cvt.u32.u64 %0, t; }"
        : "=r"(a) : "l"(p));
    return a;
}

#define SWZ64(off) ((off) ^ (((off) >> 3) & 0x30))

#define LDSM4(r, addr) \
    asm volatile("ldmatrix.sync.aligned.m8n8.x4.shared.b16 {%0,%1,%2,%3}, [%4];" \
        : "=r"((r)[0]), "=r"((r)[1]), "=r"((r)[2]), "=r"((r)[3]) : "r"(addr))
#define LDSM2(r, addr) \
    asm volatile("ldmatrix.sync.aligned.m8n8.x2.shared.b16 {%0,%1}, [%2];" \
        : "=r"((r)[0]), "=r"((r)[1]) : "r"(addr))
#define MMA_BF16(d, a, b) \
    asm volatile("mma.sync.aligned.m16n8k16.row.col.f32.bf16.bf16.f32 " \
        "{%0,%1,%2,%3}, {%4,%5,%6,%7}, {%8,%9}, {%0,%1,%2,%3};" \
        : "+f"((d)[0]), "+f"((d)[1]), "+f"((d)[2]), "+f"((d)[3]) \
        : "r"((a)[0]), "r"((a)[1]), "r"((a)[2]), "r"((a)[3]), \
          "r"((b)[0]), "r"((b)[1]))
#define CP_ASYNC16(smaddr, gptr, sz) \
    asm volatile("cp.async.cg.shared.global [%0], [%1], 16, %2;" \
        :: "r"(smaddr), "l"(gptr), "r"(sz) : "memory")

// ---------------- bf16 split helpers ----------------
__device__ __forceinline__ void split1(float v, __nv_bfloat16& h, __nv_bfloat16& l) {
    h = __float2bfloat16(v);
    l = __float2bfloat16(v - __bfloat162float(h));
}
__device__ __forceinline__ void split4_store(float4 v, __nv_bfloat16* ph, __nv_bfloat16* pl) {
    union { __nv_bfloat16 b[4]; uint2 u; } H, L;
    split1(v.x, H.b[0], L.b[0]);
    split1(v.y, H.b[1], L.b[1]);
    split1(v.z, H.b[2], L.b[2]);
    split1(v.w, H.b[3], L.b[3]);
    *(uint2*)ph = H.u;
    *(uint2*)pl = L.u;
}

// ---------------- edge dtype detection ----------------
__global__ void k_detect(const int* __restrict__ ei32) {
    __shared__ int any;
    if (threadIdx.x == 0) any = 0;
    __syncthreads();
    for (int i = threadIdx.x; i < 8192; i += blockDim.x)
        if (ei32[2 * i + 1] != 0) any = 1;
    __syncthreads();
    if (threadIdx.x == 0) g_is64 = (any == 0) ? 1 : 0;
}
__device__ __forceinline__ int edge_val(const void* ei, size_t idx) {
    if (g_is64) return (int)((const long long*)ei)[idx];
    return ((const int*)ei)[idx];
}

// ---------------- graph preprocessing ----------------
__global__ void k_zero_init() {
    int i = blockIdx.x * blockDim.x + threadIdx.x;
    if (i < NN) { g_deg[i] = 0.f; g_cursor[i] = 0; }
    if (i < 1024) g_stats[i] = 0.f;
    if (i == 0) g_total = 0;
}
__global__ void k_zero_stats() {
    int i = blockIdx.x * blockDim.x + threadIdx.x;
    if (i < 1024) g_stats[i] = 0.f;
}
__global__ void k_deg(const void* __restrict__ ei) {
    int e = blockIdx.x * blockDim.x + threadIdx.x;
    if (e >= EE) return;
    atomicAdd(&g_deg[edge_val(ei, (size_t)EE + e)], 1.f);
}
// CSR range allocation (warp scan + 1 atomic/warp) + dinv, fused.
__global__ void k_alloc() {
    int i = blockIdx.x * blockDim.x + threadIdx.x;
    int lane = threadIdx.x & 31;
    float df = (i < NN) ? g_deg[i] : 0.f;
    if (i < NN) g_dinv[i] = df > 0.f ? rsqrtf(df) : 0.f;
    int d = (int)df;
    int sum = d;
#pragma unroll
    for (int o = 1; o < 32; o <<= 1) {
        int t = __shfl_up_sync(0xFFFFFFFFu, sum, o);
        if (lane >= o) sum += t;
    }
    int excl = sum - d;
    int wtot = __shfl_sync(0xFFFFFFFFu, sum, 31);
    int base = 0;
    if (lane == 0) base = atomicAdd(&g_total, wtot);
    base = __shfl_sync(0xFFFFFFFFu, base, 0);
    if (i < NN) g_off[i] = base + excl;
}
__global__ void k_scatter(const void* __restrict__ ei) {
    int e = blockIdx.x * blockDim.x + threadIdx.x;
    if (e >= EE) return;
    int r = edge_val(ei, (size_t)e);
    int c = edge_val(ei, (size_t)EE + e);
    int pos = g_off[c] + atomicAdd(&g_cursor[c], 1);
    g_src[pos] = r;
    g_w[pos] = g_dinv[r] * g_dinv[c];
}

// x (fp32 [NN,128]) -> bf16 hi/lo into cols 0..127 of g_ah/g_al
__global__ void k_xsplit(const float* __restrict__ x) {
    int idx = blockIdx.x * blockDim.x + threadIdx.x;
    if (idx >= NN * 32) return;
    int m = idx >> 5, c = (idx & 31) * 4;
    float4 v = ((const float4*)x)[idx];
    split4_store(v, &g_ah[(size_t)m * 512 + c], &g_al[(size_t)m * 512 + c]);
}

// weight transpose+split: W [512(K)][512(N)] fp32 -> g_wb[wsel] as [N][K] bf16 hi/lo
__global__ void k_wsplit(const float* __restrict__ W, int wsel) {
    int idx = blockIdx.x * blockDim.x + threadIdx.x;
    if (idx >= 262144) return;
    int n = idx >> 9, k = idx & 511;
    float v = W[(size_t)k * 512 + n];
    __nv_bfloat16 h, l;
    split1(v, h, l);
    g_wb[(size_t)wsel * 524288 + (size_t)n * 512 + k] = h;
    g_wb[(size_t)wsel * 524288 + 262144 + (size_t)n * 512 + k] = l;
}

// W3 (4,512,16) -> g_w3b [n=k*16+j][i] bf16 hi/lo
__global__ void k_w3split(const float* __restrict__ W3) {
    int idx = blockIdx.x * blockDim.x + threadIdx.x;
    if (idx >= 32768) return;
    int k = idx >> 13;
    int r = idx & 8191;
    int i = r >> 4, j = r & 15;
    int n = k * 16 + j;
    __nv_bfloat16 h, l;
    split1(W3[idx], h, l);
    g_w3b[n * 512 + i] = h;
    g_w3b[32768 + n * 512 + i] = l;
}

// ---------------- CSR gather propagation (+ optional bf16 hi/lo emit) -------
// G threads/node, 4 cols per thread. cbase4 = column offset in float4 units.
template <int G>
__global__ void k_prop(const float* __restrict__ in_ext, size_t in_off, int in_s4,
                       size_t out_off, int out_s4, float* out_ext,
                       size_t add_off, int add_s4, int has_add,
                       const float* __restrict__ bias, int bcol, int cbase4) {
    const int per = 256 / G;
    int node = blockIdx.x * per + (int)(threadIdx.x / G);
    int lane = threadIdx.x % G;
    if (node >= NN) return;
    int s = g_off[node];
    int e = s + (int)__ldg(&g_deg[node]);
    const float4* in4 = in_ext ? (const float4*)in_ext : (const float4*)(g_buf + in_off);
    float4 acc = make_float4(0.f, 0.f, 0.f, 0.f);
    int p = s;
    for (; p + 3 < e; p += 4) {
        int   j0 = __ldg(&g_src[p]),     j1 = __ldg(&g_src[p + 1]);
        int   j2 = __ldg(&g_src[p + 2]), j3 = __ldg(&g_src[p + 3]);
        float w0 = __ldg(&g_w[p]),       w1 = __ldg(&g_w[p + 1]);
        float w2 = __ldg(&g_w[p + 2]),   w3 = __ldg(&g_w[p + 3]);
        float4 v0 = __ldg(&in4[(size_t)j0 * in_s4 + cbase4 + lane]);
        float4 v1 = __ldg(&in4[(size_t)j1 * in_s4 + cbase4 + lane]);
        float4 v2 = __ldg(&in4[(size_t)j2 * in_s4 + cbase4 + lane]);
        float4 v3 = __ldg(&in4[(size_t)j3 * in_s4 + cbase4 + lane]);
        acc.x += w0 * v0.x + w1 * v1.x + w2 * v2.x + w3 * v3.x;
        acc.y += w0 * v0.y + w1 * v1.y + w2 * v2.y + w3 * v3.y;
        acc.z += w0 * v0.z + w1 * v1.z + w2 * v2.z + w3 * v3.z;
        acc.w += w0 * v0.w + w1 * v1.w + w2 * v2.w + w3 * v3.w;
    }
    for (; p < e; ++p) {
        int   j  = __ldg(&g_src[p]);
        float wt = __ldg(&g_w[p]);
        float4 v = __ldg(&in4[(size_t)j * in_s4 + cbase4 + lane]);
        acc.x += wt * v.x; acc.y += wt * v.y;
        acc.z += wt * v.z; acc.w += wt * v.w;
    }
    if (has_add) {
        float4 a = ((const float4*)(g_buf + add_off))[(size_t)node * add_s4 + cbase4 + lane];
        acc.x += a.x; acc.y += a.y; acc.z += a.z; acc.w += a.w;
    }
    if (bias) {
        float4 b = ((const float4*)bias)[cbase4 + lane];
        acc.x += b.x; acc.y += b.y; acc.z += b.z; acc.w += b.w;
    }
    float4* out4 = out_ext ? (float4*)out_ext : (float4*)(g_buf + out_off);
    out4[(size_t)node * out_s4 + cbase4 + lane] = acc;
    if (bcol >= 0) {
        size_t bo = (size_t)node * 512 + bcol + lane * 4;
        split4_store(acc, &g_ah[bo], &g_al[bo]);
    }
}

// ---------------- bf16x3 mma.sync GEMM, cp.async 3-stage pipeline ----------
// C[M,512], CTA tile 128x128, K=512 in 16 chunks of 32.
// Stage = 4 matrices x (128 rows x 64B, SW64 swizzle) = 32KB; 3 stages = 96KB.
#define GSM_TOTAL 98304

__global__ __launch_bounds__(256, 2)
void k_gemm_mma(int wsel, size_t c_off, int M,
                const float* __restrict__ bias, int relu, int accum) {
    extern __shared__ char smem[];
    uint32_t sb = smem_u32(smem);
    int tid = threadIdx.x, wid = tid >> 5, lane = tid & 31;
    int rowBase = blockIdx.y * 128, colBase = blockIdx.x * 128;
    int warpM = (wid & 1) * 64, warpN = (wid >> 1) * 32;
    const __nv_bfloat16* Bhi = g_wb + (size_t)wsel * 524288;
    const __nv_bfloat16* Blo = Bhi + 262144;

    float acc[4][4][4];
#pragma unroll
    for (int mi = 0; mi < 4; ++mi)
#pragma unroll
        for (int ni = 0; ni < 4; ++ni)
#pragma unroll
            for (int q = 0; q < 4; ++q) acc[mi][ni][q] = 0.f;

    auto load_stage = [&](int c, int st) {
#pragma unroll
        for (int i = 0; i < 8; ++i) {
            int it = tid + i * 256;
            int mat = it >> 9;
            int idx = it & 511;
            int r = idx >> 2, u = idx & 3;
            uint32_t so = sb + (uint32_t)st * 32768 + (uint32_t)mat * 8192 +
                          SWZ64((uint32_t)(r * 64 + u * 16));
            const __nv_bfloat16* src;
            int gr, sz = 16;
            if (mat == 0)      { src = g_ah; gr = rowBase + r; if (gr >= M) { gr = 0; sz = 0; } }
            else if (mat == 1) { src = g_al; gr = rowBase + r; if (gr >= M) { gr = 0; sz = 0; } }
            else if (mat == 2) { src = Bhi; gr = colBase + r; }
            else               { src = Blo; gr = colBase + r; }
            const void* gp = src + (size_t)gr * 512 + c * 32 + u * 8;
            CP_ASYNC16(so, gp, sz);
        }
        asm volatile("cp.async.commit_group;" ::: "memory");
    };

    load_stage(0, 0);
    load_stage(1, 1);
    for (int c = 0; c < 16; ++c) {
        if (c + 2 < 16) {
            load_stage(c + 2, (c + 2) % 3);
            asm volatile("cp.async.wait_group 2;" ::: "memory");
        } else if (c + 1 < 16) {
            asm volatile("cp.async.wait_group 1;" ::: "memory");
        } else {
            asm volatile("cp.async.wait_group 0;" ::: "memory");
        }
        __syncthreads();
        uint32_t sbase = sb + (uint32_t)(c % 3) * 32768;
#pragma unroll
        for (int ks = 0; ks < 2; ++ks) {
            uint32_t bH[4][2], bL[4][2];
            int bl = lane & 15;
            int brow0 = warpN + (bl & 7);
            uint32_t bunit = ks * 2 + ((bl >> 3) & 1);
#pragma unroll
            for (int ni = 0; ni < 4; ++ni) {
                uint32_t off = SWZ64((uint32_t)((brow0 + ni * 8) * 64 + bunit * 16));
                LDSM2(bH[ni], sbase + 16384 + off);
                LDSM2(bL[ni], sbase + 24576 + off);
            }
            int arow = warpM + (lane & 15);
            uint32_t aunit = ks * 2 + (lane >> 4);
#pragma unroll
            for (int mi = 0; mi < 4; ++mi) {
                uint32_t aH[4], aL[4];
                uint32_t off = SWZ64((uint32_t)((arow + mi * 16) * 64 + aunit * 16));
                LDSM4(aH, sbase + off);
                LDSM4(aL, sbase + 8192 + off);
#pragma unroll
                for (int ni = 0; ni < 4; ++ni) {
                    MMA_BF16(acc[mi][ni], aH, bH[ni]);
                    MMA_BF16(acc[mi][ni], aH, bL[ni]);
                    MMA_BF16(acc[mi][ni], aL, bH[ni]);
                }
            }
        }
        __syncthreads();
    }

    // epilogue
    float* C = g_buf + c_off;
#pragma unroll
    for (int mi = 0; mi < 4; ++mi) {
        int r0 = rowBase + warpM + mi * 16 + (lane >> 2);
#pragma unroll
        for (int ni = 0; ni < 4; ++ni) {
            int cc = colBase + warpN + ni * 8 + (lane & 3) * 2;
            float2 v0 = make_float2(acc[mi][ni][0], acc[mi][ni][1]);
            float2 v1 = make_float2(acc[mi][ni][2], acc[mi][ni][3]);
            if (bias) {
                float2 bb = *(const float2*)&bias[cc];
                v0.x += bb.x; v0.y += bb.y;
                v1.x += bb.x; v1.y += bb.y;
            }
            if (r0 < M) {
                float* p = C + (size_t)r0 * 512 + cc;
                if (accum) { float2 o = *(float2*)p; v0.x += o.x; v0.y += o.y; }
                if (relu) { v0.x = fmaxf(v0.x, 0.f); v0.y = fmaxf(v0.y, 0.f); }
                *(float2*)p = v0;
            }
            if (r0 + 8 < M) {
                float* p = C + (size_t)(r0 + 8) * 512 + cc;
                if (accum) { float2 o = *(float2*)p; v1.x += o.x; v1.y += o.y; }
                if (relu) { v1.x = fmaxf(v1.x, 0.f); v1.y = fmaxf(v1.y, 0.f); }
                *(float2*)p = v1;
            }
        }
    }
}

// ---------------- bf16x3 mma.sync GEMM, 128x64 tile (layer 3) --------------
#define GSM64_TOTAL 49152

__global__ __launch_bounds__(256, 2)
void k_gemm_mma64(int M) {
    extern __shared__ char smem[];
    uint32_t sb = smem_u32(smem);
    int tid = threadIdx.x, wid = tid >> 5, lane = tid & 31;
    int rowBase = blockIdx.x * 128;
    int warpM = (wid & 3) * 32, warpN = (wid >> 2) * 32;

    float acc[2][4][4];
#pragma unroll
    for (int mi = 0; mi < 2; ++mi)
#pragma unroll
        for (int ni = 0; ni < 4; ++ni)
#pragma unroll
            for (int q = 0; q < 4; ++q) acc[mi][ni][q] = 0.f;

    auto load_stage = [&](int c, int st) {
#pragma unroll
        for (int i = 0; i < 6; ++i) {
            int it = tid + i * 256;
            uint32_t so;
            const void* gp;
            int sz = 16;
            if (it < 1024) {
                int hl = it >> 9, idx = it & 511;
                int r = idx >> 2, u = idx & 3;
                so = sb + (uint32_t)st * 24576 + (uint32_t)hl * 8192 +
                     SWZ64((uint32_t)(r * 64 + u * 16));
                int gr = rowBase + r;
                if (gr >= M) { gr = 0; sz = 0; }
                const __nv_bfloat16* src = hl ? g_al : g_ah;
                gp = src + (size_t)gr * 512 + c * 32 + u * 8;
            } else {
                int itb = it - 1024;
                int hl = itb >> 8, idx = itb & 255;
                int r = idx >> 2, u = idx & 3;
                so = sb + (uint32_t)st * 24576 + 16384 + (uint32_t)hl * 4096 +
                     SWZ64((uint32_t)(r * 64 + u * 16));
                gp = g_w3b + (size_t)hl * 32768 + (size_t)r * 512 + c * 32 + u * 8;
            }
            CP_ASYNC16(so, gp, sz);
        }
        asm volatile("cp.async.commit_group;" ::: "memory");
    };

    load_stage(0, 0);
    for (int c = 0; c < 16; ++c) {
        if (c + 1 < 16) {
            load_stage(c + 1, (c + 1) & 1);
            asm volatile("cp.async.wait_group 1;" ::: "memory");
        } else {
            asm volatile("cp.async.wait_group 0;" ::: "memory");
        }
        __syncthreads();
        uint32_t sbase = sb + (uint32_t)(c & 1) * 24576;
#pragma unroll
        for (int ks = 0; ks < 2; ++ks) {
            uint32_t bH[4][2], bL[4][2];
            int bl = lane & 15;
            int brow0 = warpN + (bl & 7);
            uint32_t bunit = ks * 2 + ((bl >> 3) & 1);
#pragma unroll
            for (int ni = 0; ni < 4; ++ni) {
                uint32_t off = SWZ64((uint32_t)((brow0 + ni * 8) * 64 + bunit * 16));
                LDSM2(bH[ni], sbase + 16384 + off);
                LDSM2(bL[ni], sbase + 20480 + off);
            }
            int arow = warpM + (lane & 15);
            uint32_t aunit = ks * 2 + (lane >> 4);
#pragma unroll
            for (int mi = 0; mi < 2; ++mi) {
                uint32_t aH[4], aL[4];
                uint32_t off = SWZ64((uint32_t)((arow + mi * 16) * 64 + aunit * 16));
                LDSM4(aH, sbase + off);
                LDSM4(aL, sbase + 8192 + off);
#pragma unroll
                for (int ni = 0; ni < 4; ++ni) {
                    MMA_BF16(acc[mi][ni], aH, bH[ni]);
                    MMA_BF16(acc[mi][ni], aH, bL[ni]);
                    MMA_BF16(acc[mi][ni], aL, bH[ni]);
                }
            }
        }
        __syncthreads();
    }

    float* C = g_buf + U_OFF;
#pragma unroll
    for (int mi = 0; mi < 2; ++mi) {
        int r0 = rowBase + warpM + mi * 16 + (lane >> 2);
#pragma unroll
        for (int ni = 0; ni < 4; ++ni) {
            int cc = warpN + ni * 8 + (lane & 3) * 2;
            if (r0 < M)
                *(float2*)(C + (size_t)r0 * 64 + cc) =
                    make_float2(acc[mi][ni][0], acc[mi][ni][1]);
            if (r0 + 8 < M)
                *(float2*)(C + (size_t)(r0 + 8) * 64 + cc) =
                    make_float2(acc[mi][ni][2], acc[mi][ni][3]);
        }
    }
}

// ---------------- GraphNorm ----------------
__global__ void k_stats(size_t x_off) {
    const float* x = g_buf + x_off;
    int col = threadIdx.x;
    float s = 0.f, q = 0.f;
    for (int i = blockIdx.x; i < NN; i += gridDim.x) {
        float v = x[(size_t)i * 512 + col];
        s += v;
        q += v * v;
    }
    atomicAdd(&g_stats[col], s);
    atomicAdd(&g_stats[512 + col], q);
}
__global__ void k_gnorm(size_t x_off, size_t out_off,
                        const float* __restrict__ w,
                        const float* __restrict__ b,
                        const float* __restrict__ a, int emit_bf16) {
    const float* x = g_buf + x_off;
    float* out = g_buf + out_off;
    int col = threadIdx.x;
    const float invn = 1.f / (float)NN;
    float m  = g_stats[col] * invn;
    float am = a[col] * m;
    float var = g_stats[512 + col] * invn - 2.f * am * m + am * am;
    float sc = rsqrtf(var + 1e-5f) * w[col];
    float sh = b[col];
    for (int i = blockIdx.x; i < NN; i += gridDim.x) {
        float v = (x[(size_t)i * 512 + col] - am) * sc + sh;
        out[(size_t)i * 512 + col] = v;
        if (emit_bf16) {
            __nv_bfloat16 h, l;
            split1(v, h, l);
            g_ah[(size_t)i * 512 + col] = h;
            g_al[(size_t)i * 512 + col] = l;
        }
    }
}

// ---------------- launcher ----------------
extern "C" void kernel_launch(void* const* d_in, const int* in_sizes, int n_in,
                              void* d_out, int out_size) {
    const float* x    = (const float*)d_in[0];
    const void*  ei   = d_in[1];
    const float* W1   = (const float*)d_in[2];
    const float* b1   = (const float*)d_in[3];
    const float* W2   = (const float*)d_in[4];
    const float* b2   = (const float*)d_in[5];
    const float* W3   = (const float*)d_in[6];
    const float* b3   = (const float*)d_in[7];
    const float* gn1w = (const float*)d_in[8];
    const float* gn1b = (const float*)d_in[9];
    const float* gn1a = (const float*)d_in[10];
    const float* gn2w = (const float*)d_in[11];
    const float* gn2b = (const float*)d_in[12];
    const float* gn2a = (const float*)d_in[13];
    float* out = (float*)d_out;

    cudaFuncSetAttribute(k_gemm_mma, cudaFuncAttributeMaxDynamicSharedMemorySize, GSM_TOTAL);
    cudaFuncSetAttribute(k_gemm_mma64, cudaFuncAttributeMaxDynamicSharedMemorySize, GSM64_TOTAL);

    // graph preprocessing
    k_detect<<<1, 256>>>((const int*)ei);
    k_zero_init<<<(NN + 255) / 256, 256>>>();
    k_deg<<<(EE + 255) / 256, 256>>>(ei);
    k_alloc<<<(NN + 255) / 256, 256>>>();
    k_scatter<<<(EE + 255) / 256, 256>>>(ei);

    // weight splits (independent of graph)
    k_wsplit<<<1024, 256>>>(W1, 0);
    k_wsplit<<<1024, 256>>>(W2, 1);
    k_wsplit<<<1024, 256>>>(W2 + 262144, 2);
    k_wsplit<<<1024, 256>>>(W2 + 524288, 3);
    k_wsplit<<<1024, 256>>>(W2 + 786432, 4);
    k_w3split<<<128, 256>>>(W3);

    const size_t P0 = A_OFF;                       // [NN,128] fp32 ping
    const size_t P1 = A_OFF + (size_t)NN * 128;    // [NN,128] fp32 pong
    dim3 gg(4, (NN + 127) / 128);

    // ---- layer 1: width-128 props; bf16 concat cols fill g_ah/g_al ----
    k_xsplit<<<(NN * 32 + 255) / 256, 256>>>(x);
    k_prop<32><<<(NN + 7) / 8, 256>>>(x, 0, 32, P0, 32, nullptr, 0, 0, 0, nullptr, 128, 0);
    k_prop<32><<<(NN + 7) / 8, 256>>>(nullptr, P0, 32, P1, 32, nullptr, 0, 0, 0, nullptr, 256, 0);
    k_prop<32><<<(NN + 7) / 8, 256>>>(nullptr, P1, 32, P0, 32, nullptr, 0, 0, 0, nullptr, 384, 0);
    k_gemm_mma<<<gg, 256, GSM_TOTAL>>>(0, B_OFF, NN, b1, 1, 0);

    // graphnorm 1: B -> C fp32 h0 (+bf16)
    k_stats<<<512, 512>>>(B_OFF);
    k_gnorm<<<512, 512>>>(B_OFF, C_OFF, gn1w, gn1b, gn1a, 1);

    // ---- layer 2: ACC = sum_k h_k @ W2[k]; props in 4 L2-resident quarters -
    const int PQ = (NN + 7) / 8;  // G=32: 8 nodes/block
    k_gemm_mma<<<gg, 256, GSM_TOTAL>>>(1, B_OFF, NN, b2, 0, 0);
    k_prop<32><<<PQ, 256>>>(nullptr, C_OFF, 128, A_OFF, 128, nullptr, 0, 0, 0, nullptr, 0, 0);
    k_prop<32><<<PQ, 256>>>(nullptr, C_OFF, 128, A_OFF, 128, nullptr, 0, 0, 0, nullptr, 128, 32);
    k_prop<32><<<PQ, 256>>>(nullptr, C_OFF, 128, A_OFF, 128, nullptr, 0, 0, 0, nullptr, 256, 64);
    k_prop<32><<<PQ, 256>>>(nullptr, C_OFF, 128, A_OFF, 128, nullptr, 0, 0, 0, nullptr, 384, 96);
    k_gemm_mma<<<gg, 256, GSM_TOTAL>>>(2, B_OFF, NN, nullptr, 0, 1);
    k_prop<32><<<PQ, 256>>>(nullptr, A_OFF, 128, C_OFF, 128, nullptr, 0, 0, 0, nullptr, 0, 0);
    k_prop<32><<<PQ, 256>>>(nullptr, A_OFF, 128, C_OFF, 128, nullptr, 0, 0, 0, nullptr, 128, 32);
    k_prop<32><<<PQ, 256>>>(nullptr, A_OFF, 128, C_OFF, 128, nullptr, 0, 0, 0, nullptr, 256, 64);
    k_prop<32><<<PQ, 256>>>(nullptr, A_OFF, 128, C_OFF, 128, nullptr, 0, 0, 0, nullptr, 384, 96);
    k_gemm_mma<<<gg, 256, GSM_TOTAL>>>(3, B_OFF, NN, nullptr, 0, 1);
    k_prop<32><<<PQ, 256>>>(nullptr, C_OFF, 128, A_OFF, 128, nullptr, 0, 0, 0, nullptr, 0, 0);
    k_prop<32><<<PQ, 256>>>(nullptr, C_OFF, 128, A_OFF, 128, nullptr, 0, 0, 0, nullptr, 128, 32);
    k_prop<32><<<PQ, 256>>>(nullptr, C_OFF, 128, A_OFF, 128, nullptr, 0, 0, 0, nullptr, 256, 64);
    k_prop<32><<<PQ, 256>>>(nullptr, C_OFF, 128, A_OFF, 128, nullptr, 0, 0, 0, nullptr, 384, 96);
    k_gemm_mma<<<gg, 256, GSM_TOTAL>>>(4, B_OFF, NN, nullptr, 1, 1);

    // graphnorm 2: B -> C (H2 fp32 + bf16 for layer-3 mma)
    k_zero_stats<<<4, 256>>>();
    k_stats<<<512, 512>>>(B_OFF);
    k_gnorm<<<512, 512>>>(B_OFF, C_OFF, gn2w, gn2b, gn2a, 1);

    // ---- layer 3: U = H2 @ W3t (mma), then Horner on 16-wide features ----
    k_gemm_mma64<<<(NN + 127) / 128, 256, GSM64_TOTAL>>>(NN);
    k_prop<4><<<(NN + 63) / 64, 256>>>(nullptr, U_OFF + 48, 16, T1_OFF, 4, nullptr, U_OFF + 32, 16, 1, nullptr, -1, 0);
    k_prop<4><<<(NN + 63) / 64, 256>>>(nullptr, T1_OFF, 4, T2_OFF, 4, nullptr, U_OFF + 16, 16, 1, nullptr, -1, 0);
    k_prop<4><<<(NN + 63) / 64, 256>>>(nullptr, T2_OFF, 4, 0, 4, out, U_OFF, 16, 1, b3, -1, 0);
}

// round 15
// speedup vs baseline: 1.4494x; 1.1208x over previous
#include <cuda_runtime.h>
#include <cuda_bf16.h>
#include <cuda_fp16.h>
#include <cstdint>

// Problem constants (fixed by the reference)
#define NN   100000
#define EE   3200000

// ---------------- scratch (device globals: no allocation allowed) ----------
#define NS       ((size_t)51200000)       // NN*512 floats
#define B_OFF    ((size_t)0)              // fp32 GEMM ACC / pre-norm H
#define U_OFF    (NS)                     // NN*64
#define T1_OFF   (U_OFF + 6400000)        // NN*16
#define T2_OFF   (T1_OFF + 1600000)       // NN*16
#define BUF_TOTAL (T2_OFF + 1600000)

__device__ float g_buf[BUF_TOTAL];
__device__ float g_deg[NN];
__device__ float g_dinv[NN];
__device__ int   g_off[NN + 1];
__device__ int   g_cursor[NN];
__device__ int   g_src[EE];
__device__ float g_w[EE];
__device__ float g_stats[1024];
__device__ int   g_is64;
__device__ int   g_total;

// fp16 activation ping/pong (prop inputs), bf16 hi/lo (GEMM A operand), weights
__device__ __half g_h16a[(size_t)NN * 512];
__device__ __half g_h16b[(size_t)NN * 512];
__device__ __nv_bfloat16 g_ah[(size_t)NN * 512];
__device__ __nv_bfloat16 g_al[(size_t)NN * 512];
__device__ __nv_bfloat16 g_wb[5 * 2 * 262144];
__device__ __nv_bfloat16 g_w3b[2 * 64 * 512];   // W3 transposed [64(N)][512(K)] hi/lo

// ---------------- PTX helpers (baseline ISA only — no 'a' features) --------
__device__ __forceinline__ uint32_t smem_u32(const void* p) {
    uint32_t a;
    asm("{ .reg .u64 t; cvta.to.shared.u64 t, %1; cvt.u32.u64 %0, t; }"
        : "=r"(a) : "l"(p));
    return a;
}

#define SWZ64(off) ((off) ^ (((off) >> 3) & 0x30))

#define LDSM4(r, addr) \
    asm volatile("ldmatrix.sync.aligned.m8n8.x4.shared.b16 {%0,%1,%2,%3}, [%4];" \
        : "=r"((r)[0]), "=r"((r)[1]), "=r"((r)[2]), "=r"((r)[3]) : "r"(addr))
#define LDSM2(r, addr) \
    asm volatile("ldmatrix.sync.aligned.m8n8.x2.shared.b16 {%0,%1}, [%2];" \
        : "=r"((r)[0]), "=r"((r)[1]) : "r"(addr))
#define MMA_BF16(d, a, b) \
    asm volatile("mma.sync.aligned.m16n8k16.row.col.f32.bf16.bf16.f32 " \
        "{%0,%1,%2,%3}, {%4,%5,%6,%7}, {%8,%9}, {%0,%1,%2,%3};" \
        : "+f"((d)[0]), "+f"((d)[1]), "+f"((d)[2]), "+f"((d)[3]) \
        : "r"((a)[0]), "r"((a)[1]), "r"((a)[2]), "r"((a)[3]), \
          "r"((b)[0]), "r"((b)[1]))
#define CP_ASYNC16(smaddr, gptr, sz) \
    asm volatile("cp.async.cg.shared.global [%0], [%1], 16, %2;" \
        :: "r"(smaddr), "l"(gptr), "r"(sz) : "memory")

// ---------------- bf16/fp16 helpers ----------------
__device__ __forceinline__ void split1(float v, __nv_bfloat16& h, __nv_bfloat16& l) {
    h = __float2bfloat16(v);
    l = __float2bfloat16(v - __bfloat162float(h));
}
__device__ __forceinline__ void split4_store(float4 v, __nv_bfloat16* ph, __nv_bfloat16* pl) {
    union { __nv_bfloat16 b[4]; uint2 u; } H, L;
    split1(v.x, H.b[0], L.b[0]);
    split1(v.y, H.b[1], L.b[1]);
    split1(v.z, H.b[2], L.b[2]);
    split1(v.w, H.b[3], L.b[3]);
    *(uint2*)ph = H.u;
    *(uint2*)pl = L.u;
}
__device__ __forceinline__ uint2 pack_half4(float4 v) {
    __half2 p0 = __floats2half2_rn(v.x, v.y);
    __half2 p1 = __floats2half2_rn(v.z, v.w);
    uint2 u;
    u.x = *reinterpret_cast<uint32_t*>(&p0);
    u.y = *reinterpret_cast<uint32_t*>(&p1);
    return u;
}

// ---------------- edge dtype detection ----------------
__global__ void k_detect(const int* __restrict__ ei32) {
    __shared__ int any;
    if (threadIdx.x == 0) any = 0;
    __syncthreads();
    for (int i = threadIdx.x; i < 8192; i += blockDim.x)
        if (ei32[2 * i + 1] != 0) any = 1;
    __syncthreads();
    if (threadIdx.x == 0) g_is64 = (any == 0) ? 1 : 0;
}
__device__ __forceinline__ int edge_val(const void* ei, size_t idx) {
    if (g_is64) return (int)((const long long*)ei)[idx];
    return ((const int*)ei)[idx];
}

// ---------------- graph preprocessing ----------------
__global__ void k_zero_init() {
    int i = blockIdx.x * blockDim.x + threadIdx.x;
    if (i < NN) { g_deg[i] = 0.f; g_cursor[i] = 0; }
    if (i < 1024) g_stats[i] = 0.f;
    if (i == 0) g_total = 0;
}
__global__ void k_zero_stats() {
    int i = blockIdx.x * blockDim.x + threadIdx.x;
    if (i < 1024) g_stats[i] = 0.f;
}
__global__ void k_deg(const void* __restrict__ ei) {
    int e = blockIdx.x * blockDim.x + threadIdx.x;
    if (e >= EE) return;
    atomicAdd(&g_deg[edge_val(ei, (size_t)EE + e)], 1.f);
}
// CSR range allocation (warp scan + 1 atomic/warp) + dinv, fused.
__global__ void k_alloc() {
    int i = blockIdx.x * blockDim.x + threadIdx.x;
    int lane = threadIdx.x & 31;
    float df = (i < NN) ? g_deg[i] : 0.f;
    if (i < NN) g_dinv[i] = df > 0.f ? rsqrtf(df) : 0.f;
    int d = (int)df;
    int sum = d;
#pragma unroll
    for (int o = 1; o < 32; o <<= 1) {
        int t = __shfl_up_sync(0xFFFFFFFFu, sum, o);
        if (lane >= o) sum += t;
    }
    int excl = sum - d;
    int wtot = __shfl_sync(0xFFFFFFFFu, sum, 31);
    int base = 0;
    if (lane == 0) base = atomicAdd(&g_total, wtot);
    base = __shfl_sync(0xFFFFFFFFu, base, 0);
    if (i < NN) g_off[i] = base + excl;
}
__global__ void k_scatter(const void* __restrict__ ei) {
    int e = blockIdx.x * blockDim.x + threadIdx.x;
    if (e >= EE) return;
    int r = edge_val(ei, (size_t)e);
    int c = edge_val(ei, (size_t)EE + e);
    int pos = g_off[c] + atomicAdd(&g_cursor[c], 1);
    g_src[pos] = r;
    g_w[pos] = g_dinv[r] * g_dinv[c];
}

// x (fp32 [NN,128]) -> bf16 hi/lo cols 0..127 + fp16 cols 0..127 of g_h16a
__global__ void k_xsplit(const float* __restrict__ x) {
    int idx = blockIdx.x * blockDim.x + threadIdx.x;
    if (idx >= NN * 32) return;
    int m = idx >> 5, c = (idx & 31) * 4;
    float4 v = ((const float4*)x)[idx];
    split4_store(v, &g_ah[(size_t)m * 512 + c], &g_al[(size_t)m * 512 + c]);
    *(uint2*)(g_h16a + (size_t)m * 512 + c) = pack_half4(v);
}

// weight transpose+split: W [512(K)][512(N)] fp32 -> g_wb[wsel] as [N][K] bf16 hi/lo
__global__ void k_wsplit(const float* __restrict__ W, int wsel) {
    int idx = blockIdx.x * blockDim.x + threadIdx.x;
    if (idx >= 262144) return;
    int n = idx >> 9, k = idx & 511;
    float v = W[(size_t)k * 512 + n];
    __nv_bfloat16 h, l;
    split1(v, h, l);
    g_wb[(size_t)wsel * 524288 + (size_t)n * 512 + k] = h;
    g_wb[(size_t)wsel * 524288 + 262144 + (size_t)n * 512 + k] = l;
}

// W3 (4,512,16) -> g_w3b [n=k*16+j][i] bf16 hi/lo
__global__ void k_w3split(const float* __restrict__ W3) {
    int idx = blockIdx.x * blockDim.x + threadIdx.x;
    if (idx >= 32768) return;
    int k = idx >> 13;
    int r = idx & 8191;
    int i = r >> 4, j = r & 15;
    int n = k * 16 + j;
    __nv_bfloat16 h, l;
    split1(W3[idx], h, l);
    g_w3b[n * 512 + i] = h;
    g_w3b[32768 + n * 512 + i] = l;
}

// ---------------- fp16 CSR gather prop: 128 cols per pass ------------------
// 8 nodes/CTA (G=32, 4 cols/thread). Gathers fp16, accumulates fp32,
// writes fp16 (next prop) + bf16 hi/lo (GEMM operand).
__global__ __launch_bounds__(256) void k_prop16(int in_sel, int in_cb,
                                                int out_sel, int out_cb, int bcol) {
    int node = blockIdx.x * 8 + (threadIdx.x >> 5);
    int lane = threadIdx.x & 31;
    if (node >= NN) return;
    int s = g_off[node];
    int e = s + (int)__ldg(&g_deg[node]);
    const __half* in = in_sel ? g_h16b : g_h16a;
    const int cb = in_cb + lane * 4;
    float4 acc = make_float4(0.f, 0.f, 0.f, 0.f);
    int p = s;
    for (; p + 3 < e; p += 4) {
        int   j0 = __ldg(&g_src[p]),     j1 = __ldg(&g_src[p + 1]);
        int   j2 = __ldg(&g_src[p + 2]), j3 = __ldg(&g_src[p + 3]);
        float w0 = __ldg(&g_w[p]),       w1 = __ldg(&g_w[p + 1]);
        float w2 = __ldg(&g_w[p + 2]),   w3 = __ldg(&g_w[p + 3]);
        uint2 u0 = __ldg((const uint2*)(in + (size_t)j0 * 512 + cb));
        uint2 u1 = __ldg((const uint2*)(in + (size_t)j1 * 512 + cb));
        uint2 u2 = __ldg((const uint2*)(in + (size_t)j2 * 512 + cb));
        uint2 u3 = __ldg((const uint2*)(in + (size_t)j3 * 512 + cb));
        float2 a0 = __half22float2(*reinterpret_cast<__half2*>(&u0.x));
        float2 b0 = __half22float2(*reinterpret_cast<__half2*>(&u0.y));
        float2 a1 = __half22float2(*reinterpret_cast<__half2*>(&u1.x));
        float2 b1 = __half22float2(*reinterpret_cast<__half2*>(&u1.y));
        float2 a2 = __half22float2(*reinterpret_cast<__half2*>(&u2.x));
        float2 b2 = __half22float2(*reinterpret_cast<__half2*>(&u2.y));
        float2 a3 = __half22float2(*reinterpret_cast<__half2*>(&u3.x));
        float2 b3 = __half22float2(*reinterpret_cast<__half2*>(&u3.y));
        acc.x += w0 * a0.x + w1 * a1.x + w2 * a2.x + w3 * a3.x;
        acc.y += w0 * a0.y + w1 * a1.y + w2 * a2.y + w3 * a3.y;
        acc.z += w0 * b0.x + w1 * b1.x + w2 * b2.x + w3 * b3.x;
        acc.w += w0 * b0.y + w1 * b1.y + w2 * b2.y + w3 * b3.y;
    }
    for (; p < e; ++p) {
        int   j  = __ldg(&g_src[p]);
        float wt = __ldg(&g_w[p]);
        uint2 u = __ldg((const uint2*)(in + (size_t)j * 512 + cb));
        float2 a = __half22float2(*reinterpret_cast<__half2*>(&u.x));
        float2 b = __half22float2(*reinterpret_cast<__half2*>(&u.y));
        acc.x += wt * a.x; acc.y += wt * a.y;
        acc.z += wt * b.x; acc.w += wt * b.y;
    }
    __half* outp = out_sel ? g_h16b : g_h16a;
    *(uint2*)(outp + (size_t)node * 512 + out_cb + lane * 4) = pack_half4(acc);
    if (bcol >= 0) {
        size_t bo = (size_t)node * 512 + bcol + lane * 4;
        split4_store(acc, &g_ah[bo], &g_al[bo]);
    }
}

// ---------------- fp32 CSR gather prop (layer-3 Horner, width 16) ----------
template <int G>
__global__ void k_prop(size_t in_off, int in_s4,
                       size_t out_off, int out_s4, float* out_ext,
                       size_t add_off, int add_s4, int has_add,
                       const float* __restrict__ bias) {
    const int per = 256 / G;
    int node = blockIdx.x * per + (int)(threadIdx.x / G);
    int lane = threadIdx.x % G;
    if (node >= NN) return;
    int s = g_off[node];
    int e = s + (int)__ldg(&g_deg[node]);
    const float4* in4 = (const float4*)(g_buf + in_off);
    float4 acc = make_float4(0.f, 0.f, 0.f, 0.f);
    int p = s;
    for (; p + 3 < e; p += 4) {
        int   j0 = __ldg(&g_src[p]),     j1 = __ldg(&g_src[p + 1]);
        int   j2 = __ldg(&g_src[p + 2]), j3 = __ldg(&g_src[p + 3]);
        float w0 = __ldg(&g_w[p]),       w1 = __ldg(&g_w[p + 1]);
        float w2 = __ldg(&g_w[p + 2]),   w3 = __ldg(&g_w[p + 3]);
        float4 v0 = __ldg(&in4[(size_t)j0 * in_s4 + lane]);
        float4 v1 = __ldg(&in4[(size_t)j1 * in_s4 + lane]);
        float4 v2 = __ldg(&in4[(size_t)j2 * in_s4 + lane]);
        float4 v3 = __ldg(&in4[(size_t)j3 * in_s4 + lane]);
        acc.x += w0 * v0.x + w1 * v1.x + w2 * v2.x + w3 * v3.x;
        acc.y += w0 * v0.y + w1 * v1.y + w2 * v2.y + w3 * v3.y;
        acc.z += w0 * v0.z + w1 * v1.z + w2 * v2.z + w3 * v3.z;
        acc.w += w0 * v0.w + w1 * v1.w + w2 * v2.w + w3 * v3.w;
    }
    for (; p < e; ++p) {
        int   j  = __ldg(&g_src[p]);
        float wt = __ldg(&g_w[p]);
        float4 v = __ldg(&in4[(size_t)j * in_s4 + lane]);
        acc.x += wt * v.x; acc.y += wt * v.y;
        acc.z += wt * v.z; acc.w += wt * v.w;
    }
    if (has_add) {
        float4 a = ((const float4*)(g_buf + add_off))[(size_t)node * add_s4 + lane];
        acc.x += a.x; acc.y += a.y; acc.z += a.z; acc.w += a.w;
    }
    if (bias) {
        float4 b = ((const float4*)bias)[lane];
        acc.x += b.x; acc.y += b.y; acc.z += b.z; acc.w += b.w;
    }
    float4* out4 = out_ext ? (float4*)out_ext : (float4*)(g_buf + out_off);
    out4[(size_t)node * out_s4 + lane] = acc;
}

// ---------------- bf16x3 mma.sync GEMM, cp.async 3-stage pipeline ----------
// C[M,512], CTA tile 128x128, K=512 in 16 chunks of 32.
#define GSM_TOTAL 98304

__global__ __launch_bounds__(256, 2)
void k_gemm_mma(int wsel, size_t c_off, int M,
                const float* __restrict__ bias, int relu, int accum) {
    extern __shared__ char smem[];
    uint32_t sb = smem_u32(smem);
    int tid = threadIdx.x, wid = tid >> 5, lane = tid & 31;
    int rowBase = blockIdx.y * 128, colBase = blockIdx.x * 128;
    int warpM = (wid & 1) * 64, warpN = (wid >> 1) * 32;
    const __nv_bfloat16* Bhi = g_wb + (size_t)wsel * 524288;
    const __nv_bfloat16* Blo = Bhi + 262144;

    float acc[4][4][4];
#pragma unroll
    for (int mi = 0; mi < 4; ++mi)
#pragma unroll
        for (int ni = 0; ni < 4; ++ni)
#pragma unroll
            for (int q = 0; q < 4; ++q) acc[mi][ni][q] = 0.f;

    auto load_stage = [&](int c, int st) {
#pragma unroll
        for (int i = 0; i < 8; ++i) {
            int it = tid + i * 256;
            int mat = it >> 9;
            int idx = it & 511;
            int r = idx >> 2, u = idx & 3;
            uint32_t so = sb + (uint32_t)st * 32768 + (uint32_t)mat * 8192 +
                          SWZ64((uint32_t)(r * 64 + u * 16));
            const __nv_bfloat16* src;
            int gr, sz = 16;
            if (mat == 0)      { src = g_ah; gr = rowBase + r; if (gr >= M) { gr = 0; sz = 0; } }
            else if (mat == 1) { src = g_al; gr = rowBase + r; if (gr >= M) { gr = 0; sz = 0; } }
            else if (mat == 2) { src = Bhi; gr = colBase + r; }
            else               { src = Blo; gr = colBase + r; }
            const void* gp = src + (size_t)gr * 512 + c * 32 + u * 8;
            CP_ASYNC16(so, gp, sz);
        }
        asm volatile("cp.async.commit_group;" ::: "memory");
    };

    load_stage(0, 0);
    load_stage(1, 1);
    for (int c = 0; c < 16; ++c) {
        if (c + 2 < 16) {
            load_stage(c + 2, (c + 2) % 3);
            asm volatile("cp.async.wait_group 2;" ::: "memory");
        } else if (c + 1 < 16) {
            asm volatile("cp.async.wait_group 1;" ::: "memory");
        } else {
            asm volatile("cp.async.wait_group 0;" ::: "memory");
        }
        __syncthreads();
        uint32_t sbase = sb + (uint32_t)(c % 3) * 32768;
#pragma unroll
        for (int ks = 0; ks < 2; ++ks) {
            uint32_t bH[4][2], bL[4][2];
            int bl = lane & 15;
            int brow0 = warpN + (bl & 7);
            uint32_t bunit = ks * 2 + ((bl >> 3) & 1);
#pragma unroll
            for (int ni = 0; ni < 4; ++ni) {
                uint32_t off = SWZ64((uint32_t)((brow0 + ni * 8) * 64 + bunit * 16));
                LDSM2(bH[ni], sbase + 16384 + off);
                LDSM2(bL[ni], sbase + 24576 + off);
            }
            int arow = warpM + (lane & 15);
            uint32_t aunit = ks * 2 + (lane >> 4);
#pragma unroll
            for (int mi = 0; mi < 4; ++mi) {
                uint32_t aH[4], aL[4];
                uint32_t off = SWZ64((uint32_t)((arow + mi * 16) * 64 + aunit * 16));
                LDSM4(aH, sbase + off);
                LDSM4(aL, sbase + 8192 + off);
#pragma unroll
                for (int ni = 0; ni < 4; ++ni) {
                    MMA_BF16(acc[mi][ni], aH, bH[ni]);
                    MMA_BF16(acc[mi][ni], aH, bL[ni]);
                    MMA_BF16(acc[mi][ni], aL, bH[ni]);
                }
            }
        }
        __syncthreads();
    }

    float* C = g_buf + c_off;
#pragma unroll
    for (int mi = 0; mi < 4; ++mi) {
        int r0 = rowBase + warpM + mi * 16 + (lane >> 2);
#pragma unroll
        for (int ni = 0; ni < 4; ++ni) {
            int cc = colBase + warpN + ni * 8 + (lane & 3) * 2;
            float2 v0 = make_float2(acc[mi][ni][0], acc[mi][ni][1]);
            float2 v1 = make_float2(acc[mi][ni][2], acc[mi][ni][3]);
            if (bias) {
                float2 bb = *(const float2*)&bias[cc];
                v0.x += bb.x; v0.y += bb.y;
                v1.x += bb.x; v1.y += bb.y;
            }
            if (r0 < M) {
                float* p = C + (size_t)r0 * 512 + cc;
                if (accum) { float2 o = *(float2*)p; v0.x += o.x; v0.y += o.y; }
                if (relu) { v0.x = fmaxf(v0.x, 0.f); v0.y = fmaxf(v0.y, 0.f); }
                *(float2*)p = v0;
            }
            if (r0 + 8 < M) {
                float* p = C + (size_t)(r0 + 8) * 512 + cc;
                if (accum) { float2 o = *(float2*)p; v1.x += o.x; v1.y += o.y; }
                if (relu) { v1.x = fmaxf(v1.x, 0.f); v1.y = fmaxf(v1.y, 0.f); }
                *(float2*)p = v1;
            }
        }
    }
}

// ---------------- bf16x3 mma.sync GEMM, 128x64 tile (layer 3) --------------
#define GSM64_TOTAL 49152

__global__ __launch_bounds__(256, 2)
void k_gemm_mma64(int M) {
    extern __shared__ char smem[];
    uint32_t sb = smem_u32(smem);
    int tid = threadIdx.x, wid = tid >> 5, lane = tid & 31;
    int rowBase = blockIdx.x * 128;
    int warpM = (wid & 3) * 32, warpN = (wid >> 2) * 32;

    float acc[2][4][4];
#pragma unroll
    for (int mi = 0; mi < 2; ++mi)
#pragma unroll
        for (int ni = 0; ni < 4; ++ni)
#pragma unroll
            for (int q = 0; q < 4; ++q) acc[mi][ni][q] = 0.f;

    auto load_stage = [&](int c, int st) {
#pragma unroll
        for (int i = 0; i < 6; ++i) {
            int it = tid + i * 256;
            uint32_t so;
            const void* gp;
            int sz = 16;
            if (it < 1024) {
                int hl = it >> 9, idx = it & 511;
                int r = idx >> 2, u = idx & 3;
                so = sb + (uint32_t)st * 24576 + (uint32_t)hl * 8192 +
                     SWZ64((uint32_t)(r * 64 + u * 16));
                int gr = rowBase + r;
                if (gr >= M) { gr = 0; sz = 0; }
                const __nv_bfloat16* src = hl ? g_al : g_ah;
                gp = src + (size_t)gr * 512 + c * 32 + u * 8;
            } else {
                int itb = it - 1024;
                int hl = itb >> 8, idx = itb & 255;
                int r = idx >> 2, u = idx & 3;
                so = sb + (uint32_t)st * 24576 + 16384 + (uint32_t)hl * 4096 +
                     SWZ64((uint32_t)(r * 64 + u * 16));
                gp = g_w3b + (size_t)hl * 32768 + (size_t)r * 512 + c * 32 + u * 8;
            }
            CP_ASYNC16(so, gp, sz);
        }
        asm volatile("cp.async.commit_group;" ::: "memory");
    };

    load_stage(0, 0);
    for (int c = 0; c < 16; ++c) {
        if (c + 1 < 16) {
            load_stage(c + 1, (c + 1) & 1);
            asm volatile("cp.async.wait_group 1;" ::: "memory");
        } else {
            asm volatile("cp.async.wait_group 0;" ::: "memory");
        }
        __syncthreads();
        uint32_t sbase = sb + (uint32_t)(c & 1) * 24576;
#pragma unroll
        for (int ks = 0; ks < 2; ++ks) {
            uint32_t bH[4][2], bL[4][2];
            int bl = lane & 15;
            int brow0 = warpN + (bl & 7);
            uint32_t bunit = ks * 2 + ((bl >> 3) & 1);
#pragma unroll
            for (int ni = 0; ni < 4; ++ni) {
                uint32_t off = SWZ64((uint32_t)((brow0 + ni * 8) * 64 + bunit * 16));
                LDSM2(bH[ni], sbase + 16384 + off);
                LDSM2(bL[ni], sbase + 20480 + off);
            }
            int arow = warpM + (lane & 15);
            uint32_t aunit = ks * 2 + (lane >> 4);
#pragma unroll
            for (int mi = 0; mi < 2; ++mi) {
                uint32_t aH[4], aL[4];
                uint32_t off = SWZ64((uint32_t)((arow + mi * 16) * 64 + aunit * 16));
                LDSM4(aH, sbase + off);
                LDSM4(aL, sbase + 8192 + off);
#pragma unroll
                for (int ni = 0; ni < 4; ++ni) {
                    MMA_BF16(acc[mi][ni], aH, bH[ni]);
                    MMA_BF16(acc[mi][ni], aH, bL[ni]);
                    MMA_BF16(acc[mi][ni], aL, bH[ni]);
                }
            }
        }
        __syncthreads();
    }

    float* C = g_buf + U_OFF;
#pragma unroll
    for (int mi = 0; mi < 2; ++mi) {
        int r0 = rowBase + warpM + mi * 16 + (lane >> 2);
#pragma unroll
        for (int ni = 0; ni < 4; ++ni) {
            int cc = warpN + ni * 8 + (lane & 3) * 2;
            if (r0 < M)
                *(float2*)(C + (size_t)r0 * 64 + cc) =
                    make_float2(acc[mi][ni][0], acc[mi][ni][1]);
            if (r0 + 8 < M)
                *(float2*)(C + (size_t)(r0 + 8) * 64 + cc) =
                    make_float2(acc[mi][ni][2], acc[mi][ni][3]);
        }
    }
}

// ---------------- GraphNorm ----------------
__global__ void k_stats(size_t x_off) {
    const float* x = g_buf + x_off;
    int col = threadIdx.x;
    float s = 0.f, q = 0.f;
    for (int i = blockIdx.x; i < NN; i += gridDim.x) {
        float v = x[(size_t)i * 512 + col];
        s += v;
        q += v * v;
    }
    atomicAdd(&g_stats[col], s);
    atomicAdd(&g_stats[512 + col], q);
}
// normalize; emit bf16 hi/lo always; emit fp16 into g_h16a/b when h16_sel >= 0
__global__ void k_gnorm(size_t x_off,
                        const float* __restrict__ w,
                        const float* __restrict__ b,
                        const float* __restrict__ a, int h16_sel) {
    const float* x = g_buf + x_off;
    int col = threadIdx.x;
    const float invn = 1.f / (float)NN;
    float m  = g_stats[col] * invn;
    float am = a[col] * m;
    float var = g_stats[512 + col] * invn - 2.f * am * m + am * am;
    float sc = rsqrtf(var + 1e-5f) * w[col];
    float sh = b[col];
    __half* h16 = (h16_sel == 1) ? g_h16b : g_h16a;
    for (int i = blockIdx.x; i < NN; i += gridDim.x) {
        float v = (x[(size_t)i * 512 + col] - am) * sc + sh;
        __nv_bfloat16 h, l;
        split1(v, h, l);
        g_ah[(size_t)i * 512 + col] = h;
        g_al[(size_t)i * 512 + col] = l;
        if (h16_sel >= 0)
            h16[(size_t)i * 512 + col] = __float2half_rn(v);
    }
}

// ---------------- launcher ----------------
extern "C" void kernel_launch(void* const* d_in, const int* in_sizes, int n_in,
                              void* d_out, int out_size) {
    const float* x    = (const float*)d_in[0];
    const void*  ei   = d_in[1];
    const float* W1   = (const float*)d_in[2];
    const float* b1   = (const float*)d_in[3];
    const float* W2   = (const float*)d_in[4];
    const float* b2   = (const float*)d_in[5];
    const float* W3   = (const float*)d_in[6];
    const float* b3   = (const float*)d_in[7];
    const float* gn1w = (const float*)d_in[8];
    const float* gn1b = (const float*)d_in[9];
    const float* gn1a = (const float*)d_in[10];
    const float* gn2w = (const float*)d_in[11];
    const float* gn2b = (const float*)d_in[12];
    const float* gn2a = (const float*)d_in[13];
    float* out = (float*)d_out;

    cudaFuncSetAttribute(k_gemm_mma, cudaFuncAttributeMaxDynamicSharedMemorySize, GSM_TOTAL);
    cudaFuncSetAttribute(k_gemm_mma64, cudaFuncAttributeMaxDynamicSharedMemorySize, GSM64_TOTAL);

    // graph preprocessing
    k_detect<<<1, 256>>>((const int*)ei);
    k_zero_init<<<(NN + 255) / 256, 256>>>();
    k_deg<<<(EE + 255) / 256, 256>>>(ei);
    k_alloc<<<(NN + 255) / 256, 256>>>();
    k_scatter<<<(EE + 255) / 256, 256>>>(ei);

    // weight splits (independent of graph)
    k_wsplit<<<1024, 256>>>(W1, 0);
    k_wsplit<<<1024, 256>>>(W2, 1);
    k_wsplit<<<1024, 256>>>(W2 + 262144, 2);
    k_wsplit<<<1024, 256>>>(W2 + 524288, 3);
    k_wsplit<<<1024, 256>>>(W2 + 786432, 4);
    k_w3split<<<128, 256>>>(W3);

    const int PB = (NN + 7) / 8;  // 12500 CTAs, 8 nodes each
    dim3 gg(4, (NN + 127) / 128);

    // ---- layer 1: fp16 hops in col-blocks of g_h16a; bf16 concat emit ----
    k_xsplit<<<(NN * 32 + 255) / 256, 256>>>(x);
    k_prop16<<<PB, 256>>>(0, 0,   0, 128, 128);
    k_prop16<<<PB, 256>>>(0, 128, 0, 256, 256);
    k_prop16<<<PB, 256>>>(0, 256, 0, 384, 384);
    k_gemm_mma<<<gg, 256, GSM_TOTAL>>>(0, B_OFF, NN, b1, 1, 0);

    // graphnorm 1: B -> h0 (fp16 into g_h16a + bf16)
    k_stats<<<512, 512>>>(B_OFF);
    k_gnorm<<<512, 512>>>(B_OFF, gn1w, gn1b, gn1a, 0);

    // ---- layer 2: ACC = sum_k h_k @ W2[k]; fp16 props in 4 quarters ----
    k_gemm_mma<<<gg, 256, GSM_TOTAL>>>(1, B_OFF, NN, b2, 0, 0);
    k_prop16<<<PB, 256>>>(0, 0,   1, 0,   0);     // h0(a) -> h1(b)
    k_prop16<<<PB, 256>>>(0, 128, 1, 128, 128);
    k_prop16<<<PB, 256>>>(0, 256, 1, 256, 256);
    k_prop16<<<PB, 256>>>(0, 384, 1, 384, 384);
    k_gemm_mma<<<gg, 256, GSM_TOTAL>>>(2, B_OFF, NN, nullptr, 0, 1);
    k_prop16<<<PB, 256>>>(1, 0,   0, 0,   0);     // h1(b) -> h2(a)
    k_prop16<<<PB, 256>>>(1, 128, 0, 128, 128);
    k_prop16<<<PB, 256>>>(1, 256, 0, 256, 256);
    k_prop16<<<PB, 256>>>(1, 384, 0, 384, 384);
    k_gemm_mma<<<gg, 256, GSM_TOTAL>>>(3, B_OFF, NN, nullptr, 0, 1);
    k_prop16<<<PB, 256>>>(0, 0,   1, 0,   0);     // h2(a) -> h3(b)
    k_prop16<<<PB, 256>>>(0, 128, 1, 128, 128);
    k_prop16<<<PB, 256>>>(0, 256, 1, 256, 256);
    k_prop16<<<PB, 256>>>(0, 384, 1, 384, 384);
    k_gemm_mma<<<gg, 256, GSM_TOTAL>>>(4, B_OFF, NN, nullptr, 1, 1);

    // graphnorm 2: B -> H2 (bf16 only, for layer-3 mma)
    k_zero_stats<<<4, 256>>>();
    k_stats<<<512, 512>>>(B_OFF);
    k_gnorm<<<512, 512>>>(B_OFF, gn2w, gn2b, gn2a, -1);

    // ---- layer 3: U = H2 @ W3t (mma), then Horner on 16-wide features ----
    k_gemm_mma64<<<(NN + 127) / 128, 256, GSM64_TOTAL>>>(NN);
    k_prop<4><<<(NN + 63) / 64, 256>>>(U_OFF + 48, 16, T1_OFF, 4, nullptr, U_OFF + 32, 16, 1, nullptr);
    k_prop<4><<<(NN + 63) / 64, 256>>>(T1_OFF, 4, T2_OFF, 4, nullptr, U_OFF + 16, 16, 1, nullptr);
    k_prop<4><<<(NN + 63) / 64, 256>>>(T2_OFF, 4, 0, 4, out, U_OFF, 16, 1, b3);
}

// round 16
// speedup vs baseline: 1.9882x; 1.3717x over previous
#include <cuda_runtime.h>
#include <cuda_bf16.h>
#include <cuda_fp16.h>
#include <cstdint>

// Problem constants (fixed by the reference)
#define NN   100000
#define EE   3200000

// ---------------- scratch (device globals: no allocation allowed) ----------
#define NS       ((size_t)51200000)       // NN*512 floats
#define B_OFF    ((size_t)0)              // fp32 GEMM ACC / pre-norm H
#define U_OFF    (NS)                     // NN*64
#define T1_OFF   (U_OFF + 6400000)        // NN*16
#define T2_OFF   (T1_OFF + 1600000)       // NN*16
#define BUF_TOTAL (T2_OFF + 1600000)

__device__ float g_buf[BUF_TOTAL];
__device__ float g_deg[NN];
__device__ float g_dinv[NN];
__device__ int   g_off[NN + 1];
__device__ int   g_cursor[NN];
__device__ int   g_src[EE];
__device__ float g_w[EE];
__device__ float g_stats[1024];
__device__ int   g_is64;
__device__ int   g_total;

// fp16 activation ping/pong (prop inputs AND GEMM A operands), fp16 weights
__device__ __half g_h16a[(size_t)NN * 512];
__device__ __half g_h16b[(size_t)NN * 512];
__device__ __half g_wh[5 * 262144];       // 5 x [N=512][K=512] fp16
__device__ __half g_w3h[64 * 512];        // W3 transposed [64(N)][512(K)] fp16

// ---------------- PTX helpers (baseline ISA only — no 'a' features) --------
__device__ __forceinline__ uint32_t smem_u32(const void* p) {
    uint32_t a;
    asm("{ .reg .u64 t; cvta.to.shared.u64 t, %1; cvt.u32.u64 %0, t; }"
        : "=r"(a) : "l"(p));
    return a;
}

#define SWZ64(off) ((off) ^ (((off) >> 3) & 0x30))

#define LDSM4(r, addr) \
    asm volatile("ldmatrix.sync.aligned.m8n8.x4.shared.b16 {%0,%1,%2,%3}, [%4];" \
        : "=r"((r)[0]), "=r"((r)[1]), "=r"((r)[2]), "=r"((r)[3]) : "r"(addr))
#define LDSM2(r, addr) \
    asm volatile("ldmatrix.sync.aligned.m8n8.x2.shared.b16 {%0,%1}, [%2];" \
        : "=r"((r)[0]), "=r"((r)[1]) : "r"(addr))
#define MMA_F16(d, a, b) \
    asm volatile("mma.sync.aligned.m16n8k16.row.col.f32.f16.f16.f32 " \
        "{%0,%1,%2,%3}, {%4,%5,%6,%7}, {%8,%9}, {%0,%1,%2,%3};" \
        : "+f"((d)[0]), "+f"((d)[1]), "+f"((d)[2]), "+f"((d)[3]) \
        : "r"((a)[0]), "r"((a)[1]), "r"((a)[2]), "r"((a)[3]), \
          "r"((b)[0]), "r"((b)[1]))
#define CP_ASYNC16(smaddr, gptr, sz) \
    asm volatile("cp.async.cg.shared.global [%0], [%1], 16, %2;" \
        :: "r"(smaddr), "l"(gptr), "r"(sz) : "memory")

// ---------------- fp16 helpers ----------------
__device__ __forceinline__ uint2 pack_half4(float4 v) {
    __half2 p0 = __floats2half2_rn(v.x, v.y);
    __half2 p1 = __floats2half2_rn(v.z, v.w);
    uint2 u;
    u.x = *reinterpret_cast<uint32_t*>(&p0);
    u.y = *reinterpret_cast<uint32_t*>(&p1);
    return u;
}

// ---------------- edge dtype detection ----------------
__global__ void k_detect(const int* __restrict__ ei32) {
    __shared__ int any;
    if (threadIdx.x == 0) any = 0;
    __syncthreads();
    for (int i = threadIdx.x; i < 8192; i += blockDim.x)
        if (ei32[2 * i + 1] != 0) any = 1;
    __syncthreads();
    if (threadIdx.x == 0) g_is64 = (any == 0) ? 1 : 0;
}
__device__ __forceinline__ int edge_val(const void* ei, size_t idx) {
    if (g_is64) return (int)((const long long*)ei)[idx];
    return ((const int*)ei)[idx];
}

// ---------------- graph preprocessing ----------------
__global__ void k_zero_init() {
    int i = blockIdx.x * blockDim.x + threadIdx.x;
    if (i < NN) { g_deg[i] = 0.f; g_cursor[i] = 0; }
    if (i < 1024) g_stats[i] = 0.f;
    if (i == 0) g_total = 0;
}
__global__ void k_zero_stats() {
    int i = blockIdx.x * blockDim.x + threadIdx.x;
    if (i < 1024) g_stats[i] = 0.f;
}
__global__ void k_deg(const void* __restrict__ ei) {
    int e = blockIdx.x * blockDim.x + threadIdx.x;
    if (e >= EE) return;
    atomicAdd(&g_deg[edge_val(ei, (size_t)EE + e)], 1.f);
}
// CSR range allocation (warp scan + 1 atomic/warp) + dinv, fused.
__global__ void k_alloc() {
    int i = blockIdx.x * blockDim.x + threadIdx.x;
    int lane = threadIdx.x & 31;
    float df = (i < NN) ? g_deg[i] : 0.f;
    if (i < NN) g_dinv[i] = df > 0.f ? rsqrtf(df) : 0.f;
    int d = (int)df;
    int sum = d;
#pragma unroll
    for (int o = 1; o < 32; o <<= 1) {
        int t = __shfl_up_sync(0xFFFFFFFFu, sum, o);
        if (lane >= o) sum += t;
    }
    int excl = sum - d;
    int wtot = __shfl_sync(0xFFFFFFFFu, sum, 31);
    int base = 0;
    if (lane == 0) base = atomicAdd(&g_total, wtot);
    base = __shfl_sync(0xFFFFFFFFu, base, 0);
    if (i < NN) g_off[i] = base + excl;
}
__global__ void k_scatter(const void* __restrict__ ei) {
    int e = blockIdx.x * blockDim.x + threadIdx.x;
    if (e >= EE) return;
    int r = edge_val(ei, (size_t)e);
    int c = edge_val(ei, (size_t)EE + e);
    int pos = g_off[c] + atomicAdd(&g_cursor[c], 1);
    g_src[pos] = r;
    g_w[pos] = g_dinv[r] * g_dinv[c];
}

// x (fp32 [NN,128]) -> fp16 cols 0..127 of g_h16a
__global__ void k_xsplit(const float* __restrict__ x) {
    int idx = blockIdx.x * blockDim.x + threadIdx.x;
    if (idx >= NN * 32) return;
    int m = idx >> 5, c = (idx & 31) * 4;
    float4 v = ((const float4*)x)[idx];
    *(uint2*)(g_h16a + (size_t)m * 512 + c) = pack_half4(v);
}

// weight transpose: W [512(K)][512(N)] fp32 -> g_wh[wsel] as [N][K] fp16
__global__ void k_wh(const float* __restrict__ W, int wsel) {
    int idx = blockIdx.x * blockDim.x + threadIdx.x;
    if (idx >= 262144) return;
    int n = idx >> 9, k = idx & 511;
    g_wh[(size_t)wsel * 262144 + (size_t)n * 512 + k] = __float2half_rn(W[(size_t)k * 512 + n]);
}

// W3 (4,512,16) -> g_w3h [n=k*16+j][i] fp16
__global__ void k_w3h(const float* __restrict__ W3) {
    int idx = blockIdx.x * blockDim.x + threadIdx.x;
    if (idx >= 32768) return;
    int k = idx >> 13;
    int r = idx & 8191;
    int i = r >> 4, j = r & 15;
    int n = k * 16 + j;
    g_w3h[n * 512 + i] = __float2half_rn(W3[idx]);
}

// ---------------- fp16 CSR gather prop: 128 cols per pass ------------------
// 8 nodes/CTA (G=32, 4 cols/thread). Gathers fp16, accumulates fp32, emits fp16.
__global__ __launch_bounds__(256) void k_prop16(int in_sel, int in_cb,
                                                int out_sel, int out_cb) {
    int node = blockIdx.x * 8 + (threadIdx.x >> 5);
    int lane = threadIdx.x & 31;
    if (node >= NN) return;
    int s = g_off[node];
    int e = s + (int)__ldg(&g_deg[node]);
    const __half* in = in_sel ? g_h16b : g_h16a;
    const int cb = in_cb + lane * 4;
    float4 acc = make_float4(0.f, 0.f, 0.f, 0.f);
    int p = s;
    for (; p + 3 < e; p += 4) {
        int   j0 = __ldg(&g_src[p]),     j1 = __ldg(&g_src[p + 1]);
        int   j2 = __ldg(&g_src[p + 2]), j3 = __ldg(&g_src[p + 3]);
        float w0 = __ldg(&g_w[p]),       w1 = __ldg(&g_w[p + 1]);
        float w2 = __ldg(&g_w[p + 2]),   w3 = __ldg(&g_w[p + 3]);
        uint2 u0 = __ldg((const uint2*)(in + (size_t)j0 * 512 + cb));
        uint2 u1 = __ldg((const uint2*)(in + (size_t)j1 * 512 + cb));
        uint2 u2 = __ldg((const uint2*)(in + (size_t)j2 * 512 + cb));
        uint2 u3 = __ldg((const uint2*)(in + (size_t)j3 * 512 + cb));
        float2 a0 = __half22float2(*reinterpret_cast<__half2*>(&u0.x));
        float2 b0 = __half22float2(*reinterpret_cast<__half2*>(&u0.y));
        float2 a1 = __half22float2(*reinterpret_cast<__half2*>(&u1.x));
        float2 b1 = __half22float2(*reinterpret_cast<__half2*>(&u1.y));
        float2 a2 = __half22float2(*reinterpret_cast<__half2*>(&u2.x));
        float2 b2 = __half22float2(*reinterpret_cast<__half2*>(&u2.y));
        float2 a3 = __half22float2(*reinterpret_cast<__half2*>(&u3.x));
        float2 b3 = __half22float2(*reinterpret_cast<__half2*>(&u3.y));
        acc.x += w0 * a0.x + w1 * a1.x + w2 * a2.x + w3 * a3.x;
        acc.y += w0 * a0.y + w1 * a1.y + w2 * a2.y + w3 * a3.y;
        acc.z += w0 * b0.x + w1 * b1.x + w2 * b2.x + w3 * b3.x;
        acc.w += w0 * b0.y + w1 * b1.y + w2 * b2.y + w3 * b3.y;
    }
    for (; p < e; ++p) {
        int   j  = __ldg(&g_src[p]);
        float wt = __ldg(&g_w[p]);
        uint2 u = __ldg((const uint2*)(in + (size_t)j * 512 + cb));
        float2 a = __half22float2(*reinterpret_cast<__half2*>(&u.x));
        float2 b = __half22float2(*reinterpret_cast<__half2*>(&u.y));
        acc.x += wt * a.x; acc.y += wt * a.y;
        acc.z += wt * b.x; acc.w += wt * b.y;
    }
    __half* outp = out_sel ? g_h16b : g_h16a;
    *(uint2*)(outp + (size_t)node * 512 + out_cb + lane * 4) = pack_half4(acc);
}

// ---------------- fp32 CSR gather prop (layer-3 Horner, width 16) ----------
template <int G>
__global__ void k_prop(size_t in_off, int in_s4,
                       size_t out_off, int out_s4, float* out_ext,
                       size_t add_off, int add_s4, int has_add,
                       const float* __restrict__ bias) {
    const int per = 256 / G;
    int node = blockIdx.x * per + (int)(threadIdx.x / G);
    int lane = threadIdx.x % G;
    if (node >= NN) return;
    int s = g_off[node];
    int e = s + (int)__ldg(&g_deg[node]);
    const float4* in4 = (const float4*)(g_buf + in_off);
    float4 acc = make_float4(0.f, 0.f, 0.f, 0.f);
    int p = s;
    for (; p + 3 < e; p += 4) {
        int   j0 = __ldg(&g_src[p]),     j1 = __ldg(&g_src[p + 1]);
        int   j2 = __ldg(&g_src[p + 2]), j3 = __ldg(&g_src[p + 3]);
        float w0 = __ldg(&g_w[p]),       w1 = __ldg(&g_w[p + 1]);
        float w2 = __ldg(&g_w[p + 2]),   w3 = __ldg(&g_w[p + 3]);
        float4 v0 = __ldg(&in4[(size_t)j0 * in_s4 + lane]);
        float4 v1 = __ldg(&in4[(size_t)j1 * in_s4 + lane]);
        float4 v2 = __ldg(&in4[(size_t)j2 * in_s4 + lane]);
        float4 v3 = __ldg(&in4[(size_t)j3 * in_s4 + lane]);
        acc.x += w0 * v0.x + w1 * v1.x + w2 * v2.x + w3 * v3.x;
        acc.y += w0 * v0.y + w1 * v1.y + w2 * v2.y + w3 * v3.y;
        acc.z += w0 * v0.z + w1 * v1.z + w2 * v2.z + w3 * v3.z;
        acc.w += w0 * v0.w + w1 * v1.w + w2 * v2.w + w3 * v3.w;
    }
    for (; p < e; ++p) {
        int   j  = __ldg(&g_src[p]);
        float wt = __ldg(&g_w[p]);
        float4 v = __ldg(&in4[(size_t)j * in_s4 + lane]);
        acc.x += wt * v.x; acc.y += wt * v.y;
        acc.z += wt * v.z; acc.w += wt * v.w;
    }
    if (has_add) {
        float4 a = ((const float4*)(g_buf + add_off))[(size_t)node * add_s4 + lane];
        acc.x += a.x; acc.y += a.y; acc.z += a.z; acc.w += a.w;
    }
    if (bias) {
        float4 b = ((const float4*)bias)[lane];
        acc.x += b.x; acc.y += b.y; acc.z += b.z; acc.w += b.w;
    }
    float4* out4 = out_ext ? (float4*)out_ext : (float4*)(g_buf + out_off);
    out4[(size_t)node * out_s4 + lane] = acc;
}

// ---------------- fp16 mma.sync GEMM, cp.async 3-stage pipeline ------------
// C[M,512], CTA tile 128x128, K=512 in 16 chunks of 32.
// Stage = A(128x64B) + B(128x64B) = 16KB, SW64; 3 stages = 48KB.
#define GSM_TOTAL 49152

__global__ __launch_bounds__(256, 2)
void k_gemm_mma(int wsel, int asel, size_t c_off, int M,
                const float* __restrict__ bias, int relu, int accum) {
    extern __shared__ char smem[];
    uint32_t sb = smem_u32(smem);
    int tid = threadIdx.x, wid = tid >> 5, lane = tid & 31;
    int rowBase = blockIdx.y * 128, colBase = blockIdx.x * 128;
    int warpM = (wid & 1) * 64, warpN = (wid >> 1) * 32;
    const __half* A = asel ? g_h16b : g_h16a;
    const __half* B = g_wh + (size_t)wsel * 262144;

    float acc[4][4][4];
#pragma unroll
    for (int mi = 0; mi < 4; ++mi)
#pragma unroll
        for (int ni = 0; ni < 4; ++ni)
#pragma unroll
            for (int q = 0; q < 4; ++q) acc[mi][ni][q] = 0.f;

    auto load_stage = [&](int c, int st) {
#pragma unroll
        for (int i = 0; i < 4; ++i) {
            int it = tid + i * 256;           // 0..1023
            int mat = it >> 9;                // 0 A, 1 B
            int idx = it & 511;
            int r = idx >> 2, u = idx & 3;
            uint32_t so = sb + (uint32_t)st * 16384 + (uint32_t)mat * 8192 +
                          SWZ64((uint32_t)(r * 64 + u * 16));
            const __half* src;
            int gr, sz = 16;
            if (mat == 0) { src = A; gr = rowBase + r; if (gr >= M) { gr = 0; sz = 0; } }
            else          { src = B; gr = colBase + r; }
            const void* gp = src + (size_t)gr * 512 + c * 32 + u * 8;
            CP_ASYNC16(so, gp, sz);
        }
        asm volatile("cp.async.commit_group;" ::: "memory");
    };

    load_stage(0, 0);
    load_stage(1, 1);
    for (int c = 0; c < 16; ++c) {
        if (c + 2 < 16) {
            load_stage(c + 2, (c + 2) % 3);
            asm volatile("cp.async.wait_group 2;" ::: "memory");
        } else if (c + 1 < 16) {
            asm volatile("cp.async.wait_group 1;" ::: "memory");
        } else {
            asm volatile("cp.async.wait_group 0;" ::: "memory");
        }
        __syncthreads();
        uint32_t sbase = sb + (uint32_t)(c % 3) * 16384;
#pragma unroll
        for (int ks = 0; ks < 2; ++ks) {
            uint32_t bF[4][2];
            int bl = lane & 15;
            int brow0 = warpN + (bl & 7);
            uint32_t bunit = ks * 2 + ((bl >> 3) & 1);
#pragma unroll
            for (int ni = 0; ni < 4; ++ni) {
                uint32_t off = SWZ64((uint32_t)((brow0 + ni * 8) * 64 + bunit * 16));
                LDSM2(bF[ni], sbase + 8192 + off);
            }
            int arow = warpM + (lane & 15);
            uint32_t aunit = ks * 2 + (lane >> 4);
#pragma unroll
            for (int mi = 0; mi < 4; ++mi) {
                uint32_t aF[4];
                uint32_t off = SWZ64((uint32_t)((arow + mi * 16) * 64 + aunit * 16));
                LDSM4(aF, sbase + off);
#pragma unroll
                for (int ni = 0; ni < 4; ++ni)
                    MMA_F16(acc[mi][ni], aF, bF[ni]);
            }
        }
        __syncthreads();
    }

    float* C = g_buf + c_off;
#pragma unroll
    for (int mi = 0; mi < 4; ++mi) {
        int r0 = rowBase + warpM + mi * 16 + (lane >> 2);
#pragma unroll
        for (int ni = 0; ni < 4; ++ni) {
            int cc = colBase + warpN + ni * 8 + (lane & 3) * 2;
            float2 v0 = make_float2(acc[mi][ni][0], acc[mi][ni][1]);
            float2 v1 = make_float2(acc[mi][ni][2], acc[mi][ni][3]);
            if (bias) {
                float2 bb = *(const float2*)&bias[cc];
                v0.x += bb.x; v0.y += bb.y;
                v1.x += bb.x; v1.y += bb.y;
            }
            if (r0 < M) {
                float* p = C + (size_t)r0 * 512 + cc;
                if (accum) { float2 o = *(float2*)p; v0.x += o.x; v0.y += o.y; }
                if (relu) { v0.x = fmaxf(v0.x, 0.f); v0.y = fmaxf(v0.y, 0.f); }
                *(float2*)p = v0;
            }
            if (r0 + 8 < M) {
                float* p = C + (size_t)(r0 + 8) * 512 + cc;
                if (accum) { float2 o = *(float2*)p; v1.x += o.x; v1.y += o.y; }
                if (relu) { v1.x = fmaxf(v1.x, 0.f); v1.y = fmaxf(v1.y, 0.f); }
                *(float2*)p = v1;
            }
        }
    }
}

// ---------------- fp16 mma.sync GEMM, 128x64 tile (layer 3) ----------------
// A = g_h16a (H2 fp16), B = g_w3h. Stage: A 8K + B 4K = 12KB; 2 stages = 24KB.
#define GSM64_TOTAL 24576

__global__ __launch_bounds__(256, 2)
void k_gemm_mma64(int M) {
    extern __shared__ char smem[];
    uint32_t sb = smem_u32(smem);
    int tid = threadIdx.x, wid = tid >> 5, lane = tid & 31;
    int rowBase = blockIdx.x * 128;
    int warpM = (wid & 3) * 32, warpN = (wid >> 2) * 32;

    float acc[2][4][4];
#pragma unroll
    for (int mi = 0; mi < 2; ++mi)
#pragma unroll
        for (int ni = 0; ni < 4; ++ni)
#pragma unroll
            for (int q = 0; q < 4; ++q) acc[mi][ni][q] = 0.f;

    auto load_stage = [&](int c, int st) {
#pragma unroll
        for (int i = 0; i < 3; ++i) {
            int it = tid + i * 256;    // 0..767
            uint32_t so;
            const void* gp;
            int sz = 16;
            if (it < 512) {            // A: 128 rows x 4 units
                int r = it >> 2, u = it & 3;
                so = sb + (uint32_t)st * 12288 + SWZ64((uint32_t)(r * 64 + u * 16));
                int gr = rowBase + r;
                if (gr >= M) { gr = 0; sz = 0; }
                gp = g_h16a + (size_t)gr * 512 + c * 32 + u * 8;
            } else {                   // B: 64 rows x 4 units
                int idx = it - 512;
                int r = idx >> 2, u = idx & 3;
                so = sb + (uint32_t)st * 12288 + 8192 + SWZ64((uint32_t)(r * 64 + u * 16));
                gp = g_w3h + (size_t)r * 512 + c * 32 + u * 8;
            }
            CP_ASYNC16(so, gp, sz);
        }
        asm volatile("cp.async.commit_group;" ::: "memory");
    };

    load_stage(0, 0);
    for (int c = 0; c < 16; ++c) {
        if (c + 1 < 16) {
            load_stage(c + 1, (c + 1) & 1);
            asm volatile("cp.async.wait_group 1;" ::: "memory");
        } else {
            asm volatile("cp.async.wait_group 0;" ::: "memory");
        }
        __syncthreads();
        uint32_t sbase = sb + (uint32_t)(c & 1) * 12288;
#pragma unroll
        for (int ks = 0; ks < 2; ++ks) {
            uint32_t bF[4][2];
            int bl = lane & 15;
            int brow0 = warpN + (bl & 7);
            uint32_t bunit = ks * 2 + ((bl >> 3) & 1);
#pragma unroll
            for (int ni = 0; ni < 4; ++ni) {
                uint32_t off = SWZ64((uint32_t)((brow0 + ni * 8) * 64 + bunit * 16));
                LDSM2(bF[ni], sbase + 8192 + off);
            }
            int arow = warpM + (lane & 15);
            uint32_t aunit = ks * 2 + (lane >> 4);
#pragma unroll
            for (int mi = 0; mi < 2; ++mi) {
                uint32_t aF[4];
                uint32_t off = SWZ64((uint32_t)((arow + mi * 16) * 64 + aunit * 16));
                LDSM4(aF, sbase + off);
#pragma unroll
                for (int ni = 0; ni < 4; ++ni)
                    MMA_F16(acc[mi][ni], aF, bF[ni]);
            }
        }
        __syncthreads();
    }

    float* C = g_buf + U_OFF;
#pragma unroll
    for (int mi = 0; mi < 2; ++mi) {
        int r0 = rowBase + warpM + mi * 16 + (lane >> 2);
#pragma unroll
        for (int ni = 0; ni < 4; ++ni) {
            int cc = warpN + ni * 8 + (lane & 3) * 2;
            if (r0 < M)
                *(float2*)(C + (size_t)r0 * 64 + cc) =
                    make_float2(acc[mi][ni][0], acc[mi][ni][1]);
            if (r0 + 8 < M)
                *(float2*)(C + (size_t)(r0 + 8) * 64 + cc) =
                    make_float2(acc[mi][ni][2], acc[mi][ni][3]);
        }
    }
}

// ---------------- GraphNorm ----------------
__global__ void k_stats(size_t x_off) {
    const float* x = g_buf + x_off;
    int col = threadIdx.x;
    float s = 0.f, q = 0.f;
    for (int i = blockIdx.x; i < NN; i += gridDim.x) {
        float v = x[(size_t)i * 512 + col];
        s += v;
        q += v * v;
    }
    atomicAdd(&g_stats[col], s);
    atomicAdd(&g_stats[512 + col], q);
}
// normalize; emit fp16 into g_h16a (sel 0) or g_h16b (sel 1)
__global__ void k_gnorm(size_t x_off,
                        const float* __restrict__ w,
                        const float* __restrict__ b,
                        const float* __restrict__ a, int h16_sel) {
    const float* x = g_buf + x_off;
    int col = threadIdx.x;
    const float invn = 1.f / (float)NN;
    float m  = g_stats[col] * invn;
    float am = a[col] * m;
    float var = g_stats[512 + col] * invn - 2.f * am * m + am * am;
    float sc = rsqrtf(var + 1e-5f) * w[col];
    float sh = b[col];
    __half* h16 = h16_sel ? g_h16b : g_h16a;
    for (int i = blockIdx.x; i < NN; i += gridDim.x) {
        float v = (x[(size_t)i * 512 + col] - am) * sc + sh;
        h16[(size_t)i * 512 + col] = __float2half_rn(v);
    }
}

// ---------------- launcher ----------------
extern "C" void kernel_launch(void* const* d_in, const int* in_sizes, int n_in,
                              void* d_out, int out_size) {
    const float* x    = (const float*)d_in[0];
    const void*  ei   = d_in[1];
    const float* W1   = (const float*)d_in[2];
    const float* b1   = (const float*)d_in[3];
    const float* W2   = (const float*)d_in[4];
    const float* b2   = (const float*)d_in[5];
    const float* W3   = (const float*)d_in[6];
    const float* b3   = (const float*)d_in[7];
    const float* gn1w = (const float*)d_in[8];
    const float* gn1b = (const float*)d_in[9];
    const float* gn1a = (const float*)d_in[10];
    const float* gn2w = (const float*)d_in[11];
    const float* gn2b = (const float*)d_in[12];
    const float* gn2a = (const float*)d_in[13];
    float* out = (float*)d_out;

    cudaFuncSetAttribute(k_gemm_mma, cudaFuncAttributeMaxDynamicSharedMemorySize, GSM_TOTAL);
    cudaFuncSetAttribute(k_gemm_mma64, cudaFuncAttributeMaxDynamicSharedMemorySize, GSM64_TOTAL);

    // graph preprocessing
    k_detect<<<1, 256>>>((const int*)ei);
    k_zero_init<<<(NN + 255) / 256, 256>>>();
    k_deg<<<(EE + 255) / 256, 256>>>(ei);
    k_alloc<<<(NN + 255) / 256, 256>>>();
    k_scatter<<<(EE + 255) / 256, 256>>>(ei);

    // weight conversion (independent of graph)
    k_wh<<<1024, 256>>>(W1, 0);
    k_wh<<<1024, 256>>>(W2, 1);
    k_wh<<<1024, 256>>>(W2 + 262144, 2);
    k_wh<<<1024, 256>>>(W2 + 524288, 3);
    k_wh<<<1024, 256>>>(W2 + 786432, 4);
    k_w3h<<<128, 256>>>(W3);

    const int PB = (NN + 7) / 8;  // 12500 CTAs, 8 nodes each
    dim3 gg(4, (NN + 127) / 128);

    // ---- layer 1: fp16 hops in col-blocks of g_h16a ----
    k_xsplit<<<(NN * 32 + 255) / 256, 256>>>(x);
    k_prop16<<<PB, 256>>>(0, 0,   0, 128);
    k_prop16<<<PB, 256>>>(0, 128, 0, 256);
    k_prop16<<<PB, 256>>>(0, 256, 0, 384);
    k_gemm_mma<<<gg, 256, GSM_TOTAL>>>(0, 0, B_OFF, NN, b1, 1, 0);

    // graphnorm 1: B -> h0 fp16 into g_h16a
    k_stats<<<512, 512>>>(B_OFF);
    k_gnorm<<<512, 512>>>(B_OFF, gn1w, gn1b, gn1a, 0);

    // ---- layer 2: ACC = sum_k h_k @ W2[k]; fp16 props in 4 quarters ----
    k_gemm_mma<<<gg, 256, GSM_TOTAL>>>(1, 0, B_OFF, NN, b2, 0, 0);
    k_prop16<<<PB, 256>>>(0, 0,   1, 0);     // h0(a) -> h1(b)
    k_prop16<<<PB, 256>>>(0, 128, 1, 128);
    k_prop16<<<PB, 256>>>(0, 256, 1, 256);
    k_prop16<<<PB, 256>>>(0, 384, 1, 384);
    k_gemm_mma<<<gg, 256, GSM_TOTAL>>>(2, 1, B_OFF, NN, nullptr, 0, 1);
    k_prop16<<<PB, 256>>>(1, 0,   0, 0);     // h1(b) -> h2(a)
    k_prop16<<<PB, 256>>>(1, 128, 0, 128);
    k_prop16<<<PB, 256>>>(1, 256, 0, 256);
    k_prop16<<<PB, 256>>>(1, 384, 0, 384);
    k_gemm_mma<<<gg, 256, GSM_TOTAL>>>(3, 0, B_OFF, NN, nullptr, 0, 1);
    k_prop16<<<PB, 256>>>(0, 0,   1, 0);     // h2(a) -> h3(b)
    k_prop16<<<PB, 256>>>(0, 128, 1, 128);
    k_prop16<<<PB, 256>>>(0, 256, 1, 256);
    k_prop16<<<PB, 256>>>(0, 384, 1, 384);
    k_gemm_mma<<<gg, 256, GSM_TOTAL>>>(4, 1, B_OFF, NN, nullptr, 1, 1);

    // graphnorm 2: B -> H2 fp16 into g_h16a (layer-3 GEMM operand)
    k_zero_stats<<<4, 256>>>();
    k_stats<<<512, 512>>>(B_OFF);
    k_gnorm<<<512, 512>>>(B_OFF, gn2w, gn2b, gn2a, 0);

    // ---- layer 3: U = H2 @ W3t (mma), then Horner on 16-wide features ----
    k_gemm_mma64<<<(NN + 127) / 128, 256, GSM64_TOTAL>>>(NN);
    k_prop<4><<<(NN + 63) / 64, 256>>>(U_OFF + 48, 16, T1_OFF, 4, nullptr, U_OFF + 32, 16, 1, nullptr);
    k_prop<4><<<(NN + 63) / 64, 256>>>(T1_OFF, 4, T2_OFF, 4, nullptr, U_OFF + 16, 16, 1, nullptr);
    k_prop<4><<<(NN + 63) / 64, 256>>>(T2_OFF, 4, 0, 4, out, U_OFF, 16, 1, b3);
}

// round 17
// speedup vs baseline: 2.3282x; 1.1710x over previous
#include <cuda_runtime.h>
#include <cuda_bf16.h>
#include <cuda_fp16.h>
#include <cstdint>

// Problem constants (fixed by the reference)
#define NN   100000
#define EE   3200000

// ---------------- scratch (device globals: no allocation allowed) ----------
#define NS       ((size_t)51200000)       // NN*512 floats
#define B_OFF    ((size_t)0)              // fp32 pre-norm H
#define U_OFF    (NS)                     // NN*64
#define T1_OFF   (U_OFF + 6400000)        // NN*16
#define T2_OFF   (T1_OFF + 1600000)       // NN*16
#define BUF_TOTAL (T2_OFF + 1600000)

__device__ float g_buf[BUF_TOTAL];
__device__ float g_deg[NN];
__device__ float g_dinv[NN];
__device__ int   g_off[NN + 1];
__device__ int   g_cursor[NN];
__device__ int   g_src[EE];
__device__ float g_w[EE];
__device__ float g_stats[1024];
__device__ int   g_is64;
__device__ int   g_total;

// fp16 concat activations [NN][2048]: layer1 concat (cols 0-511), then h0..h3
__device__ __half g_hcat[(size_t)NN * 2048];
__device__ __half g_wh1[262144];          // W1^T [512(N)][512(K)]
__device__ __half g_whcat[(size_t)512 * 2048];  // W2 concat [512(N)][2048(K)]
__device__ __half g_w3h[64 * 512];        // W3^T [64(N)][512(K)]

// ---------------- PTX helpers (baseline ISA only — no 'a' features) --------
__device__ __forceinline__ uint32_t smem_u32(const void* p) {
    uint32_t a;
    asm("{ .reg .u64 t; cvta.to.shared.u64 t, %1; cvt.u32.u64 %0, t; }"
        : "=r"(a) : "l"(p));
    return a;
}

#define SWZ64(off) ((off) ^ (((off) >> 3) & 0x30))

#define LDSM4(r, addr) \
    asm volatile("ldmatrix.sync.aligned.m8n8.x4.shared.b16 {%0,%1,%2,%3}, [%4];" \
        : "=r"((r)[0]), "=r"((r)[1]), "=r"((r)[2]), "=r"((r)[3]) : "r"(addr))
#define LDSM2(r, addr) \
    asm volatile("ldmatrix.sync.aligned.m8n8.x2.shared.b16 {%0,%1}, [%2];" \
        : "=r"((r)[0]), "=r"((r)[1]) : "r"(addr))
#define MMA_F16(d, a, b) \
    asm volatile("mma.sync.aligned.m16n8k16.row.col.f32.f16.f16.f32 " \
        "{%0,%1,%2,%3}, {%4,%5,%6,%7}, {%8,%9}, {%0,%1,%2,%3};" \
        : "+f"((d)[0]), "+f"((d)[1]), "+f"((d)[2]), "+f"((d)[3]) \
        : "r"((a)[0]), "r"((a)[1]), "r"((a)[2]), "r"((a)[3]), \
          "r"((b)[0]), "r"((b)[1]))
#define CP_ASYNC16(smaddr, gptr, sz) \
    asm volatile("cp.async.cg.shared.global [%0], [%1], 16, %2;" \
        :: "r"(smaddr), "l"(gptr), "r"(sz) : "memory")

// ---------------- fp16 helpers ----------------
__device__ __forceinline__ uint2 pack_half4(float4 v) {
    __half2 p0 = __floats2half2_rn(v.x, v.y);
    __half2 p1 = __floats2half2_rn(v.z, v.w);
    uint2 u;
    u.x = *reinterpret_cast<uint32_t*>(&p0);
    u.y = *reinterpret_cast<uint32_t*>(&p1);
    return u;
}

// ---------------- edge dtype detection ----------------
__global__ void k_detect(const int* __restrict__ ei32) {
    __shared__ int any;
    if (threadIdx.x == 0) any = 0;
    __syncthreads();
    for (int i = threadIdx.x; i < 8192; i += blockDim.x)
        if (ei32[2 * i + 1] != 0) any = 1;
    __syncthreads();
    if (threadIdx.x == 0) g_is64 = (any == 0) ? 1 : 0;
}
__device__ __forceinline__ int edge_val(const void* ei, size_t idx) {
    if (g_is64) return (int)((const long long*)ei)[idx];
    return ((const int*)ei)[idx];
}

// ---------------- graph preprocessing ----------------
__global__ void k_zero_init() {
    int i = blockIdx.x * blockDim.x + threadIdx.x;
    if (i < NN) { g_deg[i] = 0.f; g_cursor[i] = 0; }
    if (i < 1024) g_stats[i] = 0.f;
    if (i == 0) g_total = 0;
}
__global__ void k_zero_stats() {
    int i = blockIdx.x * blockDim.x + threadIdx.x;
    if (i < 1024) g_stats[i] = 0.f;
}
__global__ void k_deg(const void* __restrict__ ei) {
    int e = blockIdx.x * blockDim.x + threadIdx.x;
    if (e >= EE) return;
    atomicAdd(&g_deg[edge_val(ei, (size_t)EE + e)], 1.f);
}
// CSR range allocation (warp scan + 1 atomic/warp) + dinv, fused.
__global__ void k_alloc() {
    int i = blockIdx.x * blockDim.x + threadIdx.x;
    int lane = threadIdx.x & 31;
    float df = (i < NN) ? g_deg[i] : 0.f;
    if (i < NN) g_dinv[i] = df > 0.f ? rsqrtf(df) : 0.f;
    int d = (int)df;
    int sum = d;
#pragma unroll
    for (int o = 1; o < 32; o <<= 1) {
        int t = __shfl_up_sync(0xFFFFFFFFu, sum, o);
        if (lane >= o) sum += t;
    }
    int excl = sum - d;
    int wtot = __shfl_sync(0xFFFFFFFFu, sum, 31);
    int base = 0;
    if (lane == 0) base = atomicAdd(&g_total, wtot);
    base = __shfl_sync(0xFFFFFFFFu, base, 0);
    if (i < NN) g_off[i] = base + excl;
}
__global__ void k_scatter(const void* __restrict__ ei) {
    int e = blockIdx.x * blockDim.x + threadIdx.x;
    if (e >= EE) return;
    int r = edge_val(ei, (size_t)e);
    int c = edge_val(ei, (size_t)EE + e);
    int pos = g_off[c] + atomicAdd(&g_cursor[c], 1);
    g_src[pos] = r;
    g_w[pos] = g_dinv[r] * g_dinv[c];
}

// x (fp32 [NN,128]) -> fp16 cols 0..127 of g_hcat
__global__ void k_xsplit(const float* __restrict__ x) {
    int idx = blockIdx.x * blockDim.x + threadIdx.x;
    if (idx >= NN * 32) return;
    int m = idx >> 5, c = (idx & 31) * 4;
    float4 v = ((const float4*)x)[idx];
    *(uint2*)(g_hcat + (size_t)m * 2048 + c) = pack_half4(v);
}

// W1 [512(K)][512(N)] -> g_wh1 [N][K] fp16
__global__ void k_wh1(const float* __restrict__ W) {
    int idx = blockIdx.x * blockDim.x + threadIdx.x;
    if (idx >= 262144) return;
    int n = idx >> 9, k = idx & 511;
    g_wh1[(size_t)n * 512 + k] = __float2half_rn(W[(size_t)k * 512 + n]);
}
// W2 hop h [512(K)][512(N)] -> g_whcat [N][2048] at K-offset h*512
__global__ void k_wh2(const float* __restrict__ W, int hop) {
    int idx = blockIdx.x * blockDim.x + threadIdx.x;
    if (idx >= 262144) return;
    int n = idx >> 9, k = idx & 511;
    g_whcat[(size_t)n * 2048 + hop * 512 + k] = __float2half_rn(W[(size_t)k * 512 + n]);
}
// W3 (4,512,16) -> g_w3h [n=k*16+j][i] fp16
__global__ void k_w3h(const float* __restrict__ W3) {
    int idx = blockIdx.x * blockDim.x + threadIdx.x;
    if (idx >= 32768) return;
    int k = idx >> 13;
    int r = idx & 8191;
    int i = r >> 4, j = r & 15;
    int n = k * 16 + j;
    g_w3h[n * 512 + i] = __float2half_rn(W3[idx]);
}

// ---------------- fp16 CSR gather prop: 128 cols per pass ------------------
// 8 nodes/CTA (G=32, 4 cols/thread), on g_hcat (row stride 2048).
__global__ __launch_bounds__(256) void k_prop16(int in_cb, int out_cb) {
    int node = blockIdx.x * 8 + (threadIdx.x >> 5);
    int lane = threadIdx.x & 31;
    if (node >= NN) return;
    int s = g_off[node];
    int e = s + (int)__ldg(&g_deg[node]);
    const __half* in = g_hcat;
    const int cb = in_cb + lane * 4;
    float4 acc = make_float4(0.f, 0.f, 0.f, 0.f);
    int p = s;
    for (; p + 3 < e; p += 4) {
        int   j0 = __ldg(&g_src[p]),     j1 = __ldg(&g_src[p + 1]);
        int   j2 = __ldg(&g_src[p + 2]), j3 = __ldg(&g_src[p + 3]);
        float w0 = __ldg(&g_w[p]),       w1 = __ldg(&g_w[p + 1]);
        float w2 = __ldg(&g_w[p + 2]),   w3 = __ldg(&g_w[p + 3]);
        uint2 u0 = __ldg((const uint2*)(in + (size_t)j0 * 2048 + cb));
        uint2 u1 = __ldg((const uint2*)(in + (size_t)j1 * 2048 + cb));
        uint2 u2 = __ldg((const uint2*)(in + (size_t)j2 * 2048 + cb));
        uint2 u3 = __ldg((const uint2*)(in + (size_t)j3 * 2048 + cb));
        float2 a0 = __half22float2(*reinterpret_cast<__half2*>(&u0.x));
        float2 b0 = __half22float2(*reinterpret_cast<__half2*>(&u0.y));
        float2 a1 = __half22float2(*reinterpret_cast<__half2*>(&u1.x));
        float2 b1 = __half22float2(*reinterpret_cast<__half2*>(&u1.y));
        float2 a2 = __half22float2(*reinterpret_cast<__half2*>(&u2.x));
        float2 b2 = __half22float2(*reinterpret_cast<__half2*>(&u2.y));
        float2 a3 = __half22float2(*reinterpret_cast<__half2*>(&u3.x));
        float2 b3 = __half22float2(*reinterpret_cast<__half2*>(&u3.y));
        acc.x += w0 * a0.x + w1 * a1.x + w2 * a2.x + w3 * a3.x;
        acc.y += w0 * a0.y + w1 * a1.y + w2 * a2.y + w3 * a3.y;
        acc.z += w0 * b0.x + w1 * b1.x + w2 * b2.x + w3 * b3.x;
        acc.w += w0 * b0.y + w1 * b1.y + w2 * b2.y + w3 * b3.y;
    }
    for (; p < e; ++p) {
        int   j  = __ldg(&g_src[p]);
        float wt = __ldg(&g_w[p]);
        uint2 u = __ldg((const uint2*)(in + (size_t)j * 2048 + cb));
        float2 a = __half22float2(*reinterpret_cast<__half2*>(&u.x));
        float2 b = __half22float2(*reinterpret_cast<__half2*>(&u.y));
        acc.x += wt * a.x; acc.y += wt * a.y;
        acc.z += wt * b.x; acc.w += wt * b.y;
    }
    *(uint2*)(g_hcat + (size_t)node * 2048 + out_cb + lane * 4) = pack_half4(acc);
}

// ---------------- fp32 CSR gather prop (layer-3 Horner, width 16) ----------
template <int G>
__global__ void k_prop(size_t in_off, int in_s4,
                       size_t out_off, int out_s4, float* out_ext,
                       size_t add_off, int add_s4, int has_add,
                       const float* __restrict__ bias) {
    const int per = 256 / G;
    int node = blockIdx.x * per + (int)(threadIdx.x / G);
    int lane = threadIdx.x % G;
    if (node >= NN) return;
    int s = g_off[node];
    int e = s + (int)__ldg(&g_deg[node]);
    const float4* in4 = (const float4*)(g_buf + in_off);
    float4 acc = make_float4(0.f, 0.f, 0.f, 0.f);
    int p = s;
    for (; p + 3 < e; p += 4) {
        int   j0 = __ldg(&g_src[p]),     j1 = __ldg(&g_src[p + 1]);
        int   j2 = __ldg(&g_src[p + 2]), j3 = __ldg(&g_src[p + 3]);
        float w0 = __ldg(&g_w[p]),       w1 = __ldg(&g_w[p + 1]);
        float w2 = __ldg(&g_w[p + 2]),   w3 = __ldg(&g_w[p + 3]);
        float4 v0 = __ldg(&in4[(size_t)j0 * in_s4 + lane]);
        float4 v1 = __ldg(&in4[(size_t)j1 * in_s4 + lane]);
        float4 v2 = __ldg(&in4[(size_t)j2 * in_s4 + lane]);
        float4 v3 = __ldg(&in4[(size_t)j3 * in_s4 + lane]);
        acc.x += w0 * v0.x + w1 * v1.x + w2 * v2.x + w3 * v3.x;
        acc.y += w0 * v0.y + w1 * v1.y + w2 * v2.y + w3 * v3.y;
        acc.z += w0 * v0.z + w1 * v1.z + w2 * v2.z + w3 * v3.z;
        acc.w += w0 * v0.w + w1 * v1.w + w2 * v2.w + w3 * v3.w;
    }
    for (; p < e; ++p) {
        int   j  = __ldg(&g_src[p]);
        float wt = __ldg(&g_w[p]);
        float4 v = __ldg(&in4[(size_t)j * in_s4 + lane]);
        acc.x += wt * v.x; acc.y += wt * v.y;
        acc.z += wt * v.z; acc.w += wt * v.w;
    }
    if (has_add) {
        float4 a = ((const float4*)(g_buf + add_off))[(size_t)node * add_s4 + lane];
        acc.x += a.x; acc.y += a.y; acc.z += a.z; acc.w += a.w;
    }
    if (bias) {
        float4 b = ((const float4*)bias)[lane];
        acc.x += b.x; acc.y += b.y; acc.z += b.z; acc.w += b.w;
    }
    float4* out4 = out_ext ? (float4*)out_ext : (float4*)(g_buf + out_off);
    out4[(size_t)node * out_s4 + lane] = acc;
}

// ---------------- fp16 mma.sync GEMM, cp.async 3-stage pipeline ------------
// C[M,512] = A[g_hcat, stride 2048, K=nchunks*32] @ B^T + bias (+relu)(+stats)
// Stage = A(128x64B) + B(128x64B) = 16KB, SW64; 3 stages = 48KB.
#define GSM_TOTAL 49152

__global__ __launch_bounds__(256, 2)
void k_gemm_mma(int wsel, int nchunks, int bstride, int M,
                const float* __restrict__ bias, int relu, int do_stats) {
    extern __shared__ char smem[];
    __shared__ float sstat[256];
    uint32_t sb = smem_u32(smem);
    int tid = threadIdx.x, wid = tid >> 5, lane = tid & 31;
    int rowBase = blockIdx.y * 128, colBase = blockIdx.x * 128;
    int warpM = (wid & 1) * 64, warpN = (wid >> 1) * 32;
    const __half* A = g_hcat;
    const __half* B = wsel ? g_whcat : g_wh1;
    if (do_stats) sstat[tid] = 0.f;

    float acc[4][4][4];
#pragma unroll
    for (int mi = 0; mi < 4; ++mi)
#pragma unroll
        for (int ni = 0; ni < 4; ++ni)
#pragma unroll
            for (int q = 0; q < 4; ++q) acc[mi][ni][q] = 0.f;

    auto load_stage = [&](int c, int st) {
#pragma unroll
        for (int i = 0; i < 4; ++i) {
            int it = tid + i * 256;           // 0..1023
            int mat = it >> 9;                // 0 A, 1 B
            int idx = it & 511;
            int r = idx >> 2, u = idx & 3;
            uint32_t so = sb + (uint32_t)st * 16384 + (uint32_t)mat * 8192 +
                          SWZ64((uint32_t)(r * 64 + u * 16));
            const void* gp;
            int sz = 16;
            if (mat == 0) {
                int gr = rowBase + r;
                if (gr >= M) { gr = 0; sz = 0; }
                gp = A + (size_t)gr * 2048 + c * 32 + u * 8;
            } else {
                gp = B + (size_t)(colBase + r) * bstride + c * 32 + u * 8;
            }
            CP_ASYNC16(so, gp, sz);
        }
        asm volatile("cp.async.commit_group;" ::: "memory");
    };

    load_stage(0, 0);
    load_stage(1, 1);
    for (int c = 0; c < nchunks; ++c) {
        if (c + 2 < nchunks) {
            load_stage(c + 2, (c + 2) % 3);
            asm volatile("cp.async.wait_group 2;" ::: "memory");
        } else if (c + 1 < nchunks) {
            asm volatile("cp.async.wait_group 1;" ::: "memory");
        } else {
            asm volatile("cp.async.wait_group 0;" ::: "memory");
        }
        __syncthreads();
        uint32_t sbase = sb + (uint32_t)(c % 3) * 16384;
#pragma unroll
        for (int ks = 0; ks < 2; ++ks) {
            uint32_t bF[4][2];
            int bl = lane & 15;
            int brow0 = warpN + (bl & 7);
            uint32_t bunit = ks * 2 + ((bl >> 3) & 1);
#pragma unroll
            for (int ni = 0; ni < 4; ++ni) {
                uint32_t off = SWZ64((uint32_t)((brow0 + ni * 8) * 64 + bunit * 16));
                LDSM2(bF[ni], sbase + 8192 + off);
            }
            int arow = warpM + (lane & 15);
            uint32_t aunit = ks * 2 + (lane >> 4);
#pragma unroll
            for (int mi = 0; mi < 4; ++mi) {
                uint32_t aF[4];
                uint32_t off = SWZ64((uint32_t)((arow + mi * 16) * 64 + aunit * 16));
                LDSM4(aF, sbase + off);
#pragma unroll
                for (int ni = 0; ni < 4; ++ni)
                    MMA_F16(acc[mi][ni], aF, bF[ni]);
            }
        }
        __syncthreads();
    }

    float* C = g_buf + B_OFF;
    float lsum[8], lsq[8];   // per-thread stats for its 8 columns
#pragma unroll
    for (int q = 0; q < 8; ++q) { lsum[q] = 0.f; lsq[q] = 0.f; }
#pragma unroll
    for (int mi = 0; mi < 4; ++mi) {
        int r0 = rowBase + warpM + mi * 16 + (lane >> 2);
#pragma unroll
        for (int ni = 0; ni < 4; ++ni) {
            int cc = colBase + warpN + ni * 8 + (lane & 3) * 2;
            float2 v0 = make_float2(acc[mi][ni][0], acc[mi][ni][1]);
            float2 v1 = make_float2(acc[mi][ni][2], acc[mi][ni][3]);
            if (bias) {
                float2 bb = *(const float2*)&bias[cc];
                v0.x += bb.x; v0.y += bb.y;
                v1.x += bb.x; v1.y += bb.y;
            }
            if (r0 < M) {
                if (relu) { v0.x = fmaxf(v0.x, 0.f); v0.y = fmaxf(v0.y, 0.f); }
                *(float2*)(C + (size_t)r0 * 512 + cc) = v0;
                lsum[ni * 2] += v0.x;     lsq[ni * 2] += v0.x * v0.x;
                lsum[ni * 2 + 1] += v0.y; lsq[ni * 2 + 1] += v0.y * v0.y;
            }
            if (r0 + 8 < M) {
                if (relu) { v1.x = fmaxf(v1.x, 0.f); v1.y = fmaxf(v1.y, 0.f); }
                *(float2*)(C + (size_t)(r0 + 8) * 512 + cc) = v1;
                lsum[ni * 2] += v1.x;     lsq[ni * 2] += v1.x * v1.x;
                lsum[ni * 2 + 1] += v1.y; lsq[ni * 2 + 1] += v1.y * v1.y;
            }
        }
    }
    if (do_stats) {
        // reduce over lanes sharing the same columns (lane>>2 varies, lane&3 fixed)
#pragma unroll
        for (int q = 0; q < 8; ++q) {
#pragma unroll
            for (int o = 4; o < 32; o <<= 1) {
                lsum[q] += __shfl_xor_sync(0xFFFFFFFFu, lsum[q], o);
                lsq[q]  += __shfl_xor_sync(0xFFFFFFFFu, lsq[q], o);
            }
        }
        // lanes 0..3 hold reduced values; smem-accumulate (two warpM halves combine)
        if ((lane >> 2) == 0) {
            int cbase = warpN + (lane & 3) * 2;  // local col within 128
#pragma unroll
            for (int ni = 0; ni < 4; ++ni) {
#pragma unroll
                for (int h = 0; h < 2; ++h) {
                    int lc = cbase + ni * 8 + h;
                    atomicAdd_block(&sstat[lc], lsum[ni * 2 + h]);
                    atomicAdd_block(&sstat[128 + lc], lsq[ni * 2 + h]);
                }
            }
        }
        __syncthreads();
        if (tid < 128) {
            atomicAdd(&g_stats[colBase + tid], sstat[tid]);
            atomicAdd(&g_stats[512 + colBase + tid], sstat[128 + tid]);
        }
    }
}

// ---------------- fp16 mma.sync GEMM, 128x64 tile (layer 3) ----------------
// A = g_hcat cols 0..511 (H2 fp16), B = g_w3h. Stage 12KB; 2 stages = 24KB.
#define GSM64_TOTAL 24576

__global__ __launch_bounds__(256, 2)
void k_gemm_mma64(int M) {
    extern __shared__ char smem[];
    uint32_t sb = smem_u32(smem);
    int tid = threadIdx.x, wid = tid >> 5, lane = tid & 31;
    int rowBase = blockIdx.x * 128;
    int warpM = (wid & 3) * 32, warpN = (wid >> 2) * 32;

    float acc[2][4][4];
#pragma unroll
    for (int mi = 0; mi < 2; ++mi)
#pragma unroll
        for (int ni = 0; ni < 4; ++ni)
#pragma unroll
            for (int q = 0; q < 4; ++q) acc[mi][ni][q] = 0.f;

    auto load_stage = [&](int c, int st) {
#pragma unroll
        for (int i = 0; i < 3; ++i) {
            int it = tid + i * 256;    // 0..767
            uint32_t so;
            const void* gp;
            int sz = 16;
            if (it < 512) {            // A: 128 rows x 4 units
                int r = it >> 2, u = it & 3;
                so = sb + (uint32_t)st * 12288 + SWZ64((uint32_t)(r * 64 + u * 16));
                int gr = rowBase + r;
                if (gr >= M) { gr = 0; sz = 0; }
                gp = g_hcat + (size_t)gr * 2048 + c * 32 + u * 8;
            } else {                   // B: 64 rows x 4 units
                int idx = it - 512;
                int r = idx >> 2, u = idx & 3;
                so = sb + (uint32_t)st * 12288 + 8192 + SWZ64((uint32_t)(r * 64 + u * 16));
                gp = g_w3h + (size_t)r * 512 + c * 32 + u * 8;
            }
            CP_ASYNC16(so, gp, sz);
        }
        asm volatile("cp.async.commit_group;" ::: "memory");
    };

    load_stage(0, 0);
    for (int c = 0; c < 16; ++c) {
        if (c + 1 < 16) {
            load_stage(c + 1, (c + 1) & 1);
            asm volatile("cp.async.wait_group 1;" ::: "memory");
        } else {
            asm volatile("cp.async.wait_group 0;" ::: "memory");
        }
        __syncthreads();
        uint32_t sbase = sb + (uint32_t)(c & 1) * 12288;
#pragma unroll
        for (int ks = 0; ks < 2; ++ks) {
            uint32_t bF[4][2];
            int bl = lane & 15;
            int brow0 = warpN + (bl & 7);
            uint32_t bunit = ks * 2 + ((bl >> 3) & 1);
#pragma unroll
            for (int ni = 0; ni < 4; ++ni) {
                uint32_t off = SWZ64((uint32_t)((brow0 + ni * 8) * 64 + bunit * 16));
                LDSM2(bF[ni], sbase + 8192 + off);
            }
            int arow = warpM + (lane & 15);
            uint32_t aunit = ks * 2 + (lane >> 4);
#pragma unroll
            for (int mi = 0; mi < 2; ++mi) {
                uint32_t aF[4];
                uint32_t off = SWZ64((uint32_t)((arow + mi * 16) * 64 + aunit * 16));
                LDSM4(aF, sbase + off);
#pragma unroll
                for (int ni = 0; ni < 4; ++ni)
                    MMA_F16(acc[mi][ni], aF, bF[ni]);
            }
        }
        __syncthreads();
    }

    float* C = g_buf + U_OFF;
#pragma unroll
    for (int mi = 0; mi < 2; ++mi) {
        int r0 = rowBase + warpM + mi * 16 + (lane >> 2);
#pragma unroll
        for (int ni = 0; ni < 4; ++ni) {
            int cc = warpN + ni * 8 + (lane & 3) * 2;
            if (r0 < M)
                *(float2*)(C + (size_t)r0 * 64 + cc) =
                    make_float2(acc[mi][ni][0], acc[mi][ni][1]);
            if (r0 + 8 < M)
                *(float2*)(C + (size_t)(r0 + 8) * 64 + cc) =
                    make_float2(acc[mi][ni][2], acc[mi][ni][3]);
        }
    }
}

// ---------------- GraphNorm normalize (stats already in g_stats) -----------
// reads fp32 H (g_buf[B_OFF]) -> writes fp16 into g_hcat cols 0..511
__global__ void k_gnorm(const float* __restrict__ w,
                        const float* __restrict__ b,
                        const float* __restrict__ a) {
    const float* x = g_buf + B_OFF;
    int col = threadIdx.x;
    const float invn = 1.f / (float)NN;
    float m  = g_stats[col] * invn;
    float am = a[col] * m;
    float var = g_stats[512 + col] * invn - 2.f * am * m + am * am;
    float sc = rsqrtf(var + 1e-5f) * w[col];
    float sh = b[col];
    for (int i = blockIdx.x; i < NN; i += gridDim.x) {
        float v = (x[(size_t)i * 512 + col] - am) * sc + sh;
        g_hcat[(size_t)i * 2048 + col] = __float2half_rn(v);
    }
}

// ---------------- launcher ----------------
extern "C" void kernel_launch(void* const* d_in, const int* in_sizes, int n_in,
                              void* d_out, int out_size) {
    const float* x    = (const float*)d_in[0];
    const void*  ei   = d_in[1];
    const float* W1   = (const float*)d_in[2];
    const float* b1   = (const float*)d_in[3];
    const float* W2   = (const float*)d_in[4];
    const float* b2   = (const float*)d_in[5];
    const float* W3   = (const float*)d_in[6];
    const float* b3   = (const float*)d_in[7];
    const float* gn1w = (const float*)d_in[8];
    const float* gn1b = (const float*)d_in[9];
    const float* gn1a = (const float*)d_in[10];
    const float* gn2w = (const float*)d_in[11];
    const float* gn2b = (const float*)d_in[12];
    const float* gn2a = (const float*)d_in[13];
    float* out = (float*)d_out;

    cudaFuncSetAttribute(k_gemm_mma, cudaFuncAttributeMaxDynamicSharedMemorySize, GSM_TOTAL);
    cudaFuncSetAttribute(k_gemm_mma64, cudaFuncAttributeMaxDynamicSharedMemorySize, GSM64_TOTAL);

    // graph preprocessing
    k_detect<<<1, 256>>>((const int*)ei);
    k_zero_init<<<(NN + 255) / 256, 256>>>();
    k_deg<<<(EE + 255) / 256, 256>>>(ei);
    k_alloc<<<(NN + 255) / 256, 256>>>();
    k_scatter<<<(EE + 255) / 256, 256>>>(ei);

    // weight conversion (independent of graph)
    k_wh1<<<1024, 256>>>(W1);
    k_wh2<<<1024, 256>>>(W2, 0);
    k_wh2<<<1024, 256>>>(W2 + 262144, 1);
    k_wh2<<<1024, 256>>>(W2 + 524288, 2);
    k_wh2<<<1024, 256>>>(W2 + 786432, 3);
    k_w3h<<<128, 256>>>(W3);

    const int PB = (NN + 7) / 8;  // 12500 CTAs, 8 nodes each
    dim3 gg(4, (NN + 127) / 128);

    // ---- layer 1: fp16 hops in col-blocks 0..511 of g_hcat ----
    k_xsplit<<<(NN * 32 + 255) / 256, 256>>>(x);
    k_prop16<<<PB, 256>>>(0, 128);
    k_prop16<<<PB, 256>>>(128, 256);
    k_prop16<<<PB, 256>>>(256, 384);
    k_gemm_mma<<<gg, 256, GSM_TOTAL>>>(0, 16, 512, NN, b1, 1, 1);  // + stats

    // graphnorm 1 -> h0 fp16 into g_hcat cols 0..511, then re-zero stats
    k_gnorm<<<512, 512>>>(gn1w, gn1b, gn1a);
    k_zero_stats<<<4, 256>>>();

    // ---- layer 2: 3 hops fill col-blocks 512..2047, one K=2048 GEMM ----
    k_prop16<<<PB, 256>>>(0, 512);      // h0 -> h1
    k_prop16<<<PB, 256>>>(128, 640);
    k_prop16<<<PB, 256>>>(256, 768);
    k_prop16<<<PB, 256>>>(384, 896);
    k_prop16<<<PB, 256>>>(512, 1024);   // h1 -> h2
    k_prop16<<<PB, 256>>>(640, 1152);
    k_prop16<<<PB, 256>>>(768, 1280);
    k_prop16<<<PB, 256>>>(896, 1408);
    k_prop16<<<PB, 256>>>(1024, 1536);  // h2 -> h3
    k_prop16<<<PB, 256>>>(1152, 1664);
    k_prop16<<<PB, 256>>>(1280, 1792);
    k_prop16<<<PB, 256>>>(1408, 1920);
    k_gemm_mma<<<gg, 256, GSM_TOTAL>>>(1, 64, 2048, NN, b2, 1, 1);  // + stats

    // graphnorm 2 -> H2 fp16 into g_hcat cols 0..511
    k_gnorm<<<512, 512>>>(gn2w, gn2b, gn2a);

    // ---- layer 3: U = H2 @ W3t (mma), then Horner on 16-wide features ----
    k_gemm_mma64<<<(NN + 127) / 128, 256, GSM64_TOTAL>>>(NN);
    k_prop<4><<<(NN + 63) / 64, 256>>>(U_OFF + 48, 16, T1_OFF, 4, nullptr, U_OFF + 32, 16, 1, nullptr);
    k_prop<4><<<(NN + 63) / 64, 256>>>(T1_OFF, 4, T2_OFF, 4, nullptr, U_OFF + 16, 16, 1, nullptr);
    k_prop<4><<<(NN + 63) / 64, 256>>>(T2_OFF, 4, 0, 4, out, U_OFF, 16, 1, b3);
}